// round 14
// baseline (speedup 1.0000x reference)
#include <cuda_runtime.h>
#include <cuda_bf16.h>
#include <math.h>
#include <stdint.h>

// Problem constants
#define BATCH 2
#define SEQ   2048
#define DMODEL 1024
#define NHEADS 16
#define DK    64
#define MTOT  (BATCH*SEQ)          // 4096
#define QKV_N (3*DMODEL)           // 3072
#define KE2   (2*DMODEL)           // 2048: [hi | lo] layout width
#define KV_MS ((size_t)MTOT * DMODEL)   // per-matrix stride in g_kv

// Scratch (device globals — no allocation allowed)
__device__ __nv_bfloat16 g_xe   [(size_t)MTOT  * KE2];    // x      [hi|lo]
__device__ __nv_bfloat16 g_wqkve[(size_t)QKV_N * KE2];    // W_qkv  [hi|lo]
__device__ __nv_bfloat16 g_wute [(size_t)DMODEL* KE2];    // W_out  [hi|lo]
__device__ __nv_bfloat16 g_atte [(size_t)MTOT  * KE2];    // attn out [hi|lo]
// fused qkv output: [m][b*h][s][dk], m = {Qhi,Qlo,Khi,Klo,Vhi,Vlo} (Q pre-scaled)
__device__ __nv_bfloat16 g_kv[(size_t)6 * MTOT * DMODEL];

// ---------------------------------------------------------------------------
// helpers
// ---------------------------------------------------------------------------
__device__ __forceinline__ void pack_hilo(float a, float b, uint32_t& hi, uint32_t& lo)
{
    __nv_bfloat16 ha = __float2bfloat16_rn(a), hb = __float2bfloat16_rn(b);
    __nv_bfloat162 h; h.x = ha; h.y = hb;
    __nv_bfloat162 l;
    l.x = __float2bfloat16_rn(a - __bfloat162float(ha));
    l.y = __float2bfloat16_rn(b - __bfloat162float(hb));
    hi = *(uint32_t*)&h; lo = *(uint32_t*)&l;
}

__device__ __forceinline__ void ldm_x4(uint32_t& r0, uint32_t& r1, uint32_t& r2, uint32_t& r3,
                                       uint32_t addr)
{
    asm volatile("ldmatrix.sync.aligned.m8n8.x4.shared.b16 {%0,%1,%2,%3}, [%4];"
                 : "=r"(r0), "=r"(r1), "=r"(r2), "=r"(r3) : "r"(addr));
}

__device__ __forceinline__ void ldm_x4_t(uint32_t& r0, uint32_t& r1, uint32_t& r2, uint32_t& r3,
                                         uint32_t addr)
{
    asm volatile("ldmatrix.sync.aligned.m8n8.x4.trans.shared.b16 {%0,%1,%2,%3}, [%4];"
                 : "=r"(r0), "=r"(r1), "=r"(r2), "=r"(r3) : "r"(addr));
}

__device__ __forceinline__ void mma16816(float* d, const uint32_t* a, const uint32_t* b)
{
    asm volatile(
        "mma.sync.aligned.m16n8k16.row.col.f32.bf16.bf16.f32 "
        "{%0,%1,%2,%3}, {%4,%5,%6,%7}, {%8,%9}, {%0,%1,%2,%3};"
        : "+f"(d[0]), "+f"(d[1]), "+f"(d[2]), "+f"(d[3])
        : "r"(a[0]), "r"(a[1]), "r"(a[2]), "r"(a[3]), "r"(b[0]), "r"(b[1]));
}

__device__ __forceinline__ void cp16(uint32_t saddr, const void* gptr)
{
    asm volatile("cp.async.cg.shared.global [%0], [%1], 16;" :: "r"(saddr), "l"(gptr));
}

// ---------------------------------------------------------------------------
// Split-conversion: f32 [R,K] -> bf16 [R,2K]  ([k]=hi, [K+k]=lo)
// ---------------------------------------------------------------------------
__global__ void conv_split(const float* __restrict__ in, __nv_bfloat16* __restrict__ out,
                           int K, size_t total)
{
    size_t idx = ((size_t)blockIdx.x * blockDim.x + threadIdx.x) * 4;
    if (idx >= total) return;
    int r = (int)(idx / K);
    int k = (int)(idx % K);
    float4 v = *(const float4*)(in + idx);
    uint32_t hi01, hi23, lo01, lo23;
    pack_hilo(v.x, v.y, hi01, lo01);
    pack_hilo(v.z, v.w, hi23, lo23);
    __nv_bfloat16* o = out + (size_t)r * (2 * K) + k;
    *(uint32_t*)(o + 0) = hi01;  *(uint32_t*)(o + 2) = hi23;
    *(uint32_t*)(o + K + 0) = lo01; *(uint32_t*)(o + K + 2) = lo23;
}

// ---------------------------------------------------------------------------
// bf16 tensor-core GEMM with 3-term fragment reuse (frozen from R13):
//   C = Ahi*Bhi^T + Alo*Bhi^T + Ahi*Blo^T   (fp32 accumulate)
// ---------------------------------------------------------------------------
#define GSTAGE_BYTES 32768

template<int FUSE>
__global__ void __launch_bounds__(256, 2) gemm_bf16(
    const __nv_bfloat16* __restrict__ A, const __nv_bfloat16* __restrict__ B,
    float* __restrict__ C, int N)
{
    extern __shared__ __nv_bfloat16 gsm[];
    const uint32_t sbase = (uint32_t)__cvta_generic_to_shared(gsm);

    const int tid  = threadIdx.x;
    const int lane = tid & 31;
    const int warp = tid >> 5;
    const int wr = warp >> 2;
    const int wc = warp & 3;
    const int mBase = blockIdx.y * 128;
    const int nBase = blockIdx.x * 128;

    const int lrow = tid >> 2;
    const int lseg = tid & 3;
    const uint32_t swz0 = (uint32_t)(lrow * 32 + ((lseg ^ ((lrow >> 1) & 3)) * 8)) * 2;
    const uint32_t swz1 = (uint32_t)((lrow + 64) * 32 + ((lseg ^ (((lrow + 64) >> 1) & 3)) * 8)) * 2;
    const __nv_bfloat16* gA0 = A + (size_t)(mBase + lrow)      * KE2 + lseg * 8;
    const __nv_bfloat16* gA1 = A + (size_t)(mBase + lrow + 64) * KE2 + lseg * 8;
    const __nv_bfloat16* gB0 = B + (size_t)(nBase + lrow)      * KE2 + lseg * 8;
    const __nv_bfloat16* gB1 = B + (size_t)(nBase + lrow + 64) * KE2 + lseg * 8;

    const int arow = wr * 64 + (lane & 15);
    const int aseg = (lane >> 4) & 1;
    const int brow = wc * 32 + (lane & 7) + (((lane >> 4) & 1) << 3);
    const int bseg = (lane >> 3) & 1;

    float acc[4][4][4];
#pragma unroll
    for (int a = 0; a < 4; a++)
#pragma unroll
        for (int n = 0; n < 4; n++)
#pragma unroll
            for (int i = 0; i < 4; i++) acc[a][n][i] = 0.f;

    const int NSTEP = DMODEL / 32;     // 32 real-K steps

#pragma unroll
    for (int s = 0; s < 2; s++) {
        const uint32_t st = sbase + s * GSTAGE_BYTES;
        const int k0 = s * 32;
        cp16(st +          swz0, gA0 + k0);           cp16(st +          swz1, gA1 + k0);
        cp16(st +  8192 + swz0, gA0 + DMODEL + k0);   cp16(st +  8192 + swz1, gA1 + DMODEL + k0);
        cp16(st + 16384 + swz0, gB0 + k0);            cp16(st + 16384 + swz1, gB1 + k0);
        cp16(st + 24576 + swz0, gB0 + DMODEL + k0);   cp16(st + 24576 + swz1, gB1 + DMODEL + k0);
        asm volatile("cp.async.commit_group;");
    }

    int cur = 0, nxt = 2;
    for (int t = 0; t < NSTEP; t++) {
        if (t + 1 < NSTEP) asm volatile("cp.async.wait_group 1;");
        else               asm volatile("cp.async.wait_group 0;");
        __syncthreads();

        if (t + 2 < NSTEP) {
            const uint32_t st = sbase + nxt * GSTAGE_BYTES;
            const int k0 = (t + 2) * 32;
            cp16(st +          swz0, gA0 + k0);           cp16(st +          swz1, gA1 + k0);
            cp16(st +  8192 + swz0, gA0 + DMODEL + k0);   cp16(st +  8192 + swz1, gA1 + DMODEL + k0);
            cp16(st + 16384 + swz0, gB0 + k0);            cp16(st + 16384 + swz1, gB1 + k0);
            cp16(st + 24576 + swz0, gB0 + DMODEL + k0);   cp16(st + 24576 + swz1, gB1 + DMODEL + k0);
            asm volatile("cp.async.commit_group;");
        }

        const uint32_t stg = sbase + cur * GSTAGE_BYTES;

#pragma unroll
        for (int kk = 0; kk < 2; kk++) {
            uint32_t ah[4][4];
#pragma unroll
            for (int a = 0; a < 4; a++) {
                int r = arow + a * 16;
                int seg = (kk * 2 + aseg) ^ ((r >> 1) & 3);
                ldm_x4(ah[a][0], ah[a][1], ah[a][2], ah[a][3],
                       stg + (uint32_t)(r * 32 + seg * 8) * 2);
            }
            uint32_t bh[4][2];
#pragma unroll
            for (int p = 0; p < 2; p++) {
                int n = brow + p * 16;
                int seg = (kk * 2 + bseg) ^ ((n >> 1) & 3);
                uint32_t r0, r1, r2, r3;
                ldm_x4(r0, r1, r2, r3, stg + 16384 + (uint32_t)(n * 32 + seg * 8) * 2);
                bh[p * 2 + 0][0] = r0; bh[p * 2 + 0][1] = r1;
                bh[p * 2 + 1][0] = r2; bh[p * 2 + 1][1] = r3;
            }
#pragma unroll
            for (int a = 0; a < 4; a++)
#pragma unroll
                for (int n = 0; n < 4; n++)
                    mma16816(acc[a][n], ah[a], bh[n]);

            {
                uint32_t al[4][4];
#pragma unroll
                for (int a = 0; a < 4; a++) {
                    int r = arow + a * 16;
                    int seg = (kk * 2 + aseg) ^ ((r >> 1) & 3);
                    ldm_x4(al[a][0], al[a][1], al[a][2], al[a][3],
                           stg + 8192 + (uint32_t)(r * 32 + seg * 8) * 2);
                }
#pragma unroll
                for (int a = 0; a < 4; a++)
#pragma unroll
                    for (int n = 0; n < 4; n++)
                        mma16816(acc[a][n], al[a], bh[n]);
            }
            {
                uint32_t bl[4][2];
#pragma unroll
                for (int p = 0; p < 2; p++) {
                    int n = brow + p * 16;
                    int seg = (kk * 2 + bseg) ^ ((n >> 1) & 3);
                    uint32_t r0, r1, r2, r3;
                    ldm_x4(r0, r1, r2, r3, stg + 24576 + (uint32_t)(n * 32 + seg * 8) * 2);
                    bl[p * 2 + 0][0] = r0; bl[p * 2 + 0][1] = r1;
                    bl[p * 2 + 1][0] = r2; bl[p * 2 + 1][1] = r3;
                }
#pragma unroll
                for (int a = 0; a < 4; a++)
#pragma unroll
                    for (int n = 0; n < 4; n++)
                        mma16816(acc[a][n], ah[a], bl[n]);
            }
        }
        cur = (cur == 2) ? 0 : cur + 1;
        nxt = (nxt == 2) ? 0 : nxt + 1;
    }

    if (FUSE) {
        __syncthreads();
        const int region = nBase >> 10;                // 0=Q,1=K,2=V
        const int colbase = nBase & 1023;
        const float scale = (region == 0) ? 0.125f : 1.0f;
        char* smc = (char*)gsm;

#pragma unroll
        for (int a = 0; a < 4; a++) {
            int r0_ = wr * 64 + a * 16 + (lane >> 2);
#pragma unroll
            for (int n = 0; n < 4; n++) {
                int lcol = wc * 32 + n * 8 + (lane & 3) * 2;
                int chunk = lcol >> 3;
                int inb   = (lcol * 2) & 15;
                uint32_t hi, lo;
                pack_hilo(acc[a][n][0] * scale, acc[a][n][1] * scale, hi, lo);
                {
                    uint32_t byte = (uint32_t)r0_ * 256 + (((chunk ^ (r0_ & 7)) << 4) + inb);
                    *(uint32_t*)(smc + byte)         = hi;
                    *(uint32_t*)(smc + 32768 + byte) = lo;
                }
                pack_hilo(acc[a][n][2] * scale, acc[a][n][3] * scale, hi, lo);
                {
                    int r1_ = r0_ + 8;
                    uint32_t byte = (uint32_t)r1_ * 256 + (((chunk ^ (r1_ & 7)) << 4) + inb);
                    *(uint32_t*)(smc + byte)         = hi;
                    *(uint32_t*)(smc + 32768 + byte) = lo;
                }
            }
        }
        __syncthreads();

        __nv_bfloat16* mhi = g_kv + (size_t)(2 * region)     * KV_MS;
        __nv_bfloat16* mlo = g_kv + (size_t)(2 * region + 1) * KV_MS;
#pragma unroll
        for (int j = 0; j < 8; j++) {
            int it = tid + j * 256;
            int r_ = it >> 4;
            int ch = it & 15;
            uint32_t byte = (uint32_t)r_ * 256 + ((ch ^ (r_ & 7)) << 4);
            uint4 vh = *(uint4*)(smc + byte);
            uint4 vl = *(uint4*)(smc + 32768 + byte);
            int grow = mBase + r_;
            int col = colbase + ch * 8;
            int hh = col >> 6, dd = col & 63;
            int bb_ = grow >> 11, ss = grow & 2047;
            size_t dst = (((size_t)(bb_ * NHEADS + hh)) * SEQ + ss) * DK + dd;
            *(uint4*)&mhi[dst] = vh;
            *(uint4*)&mlo[dst] = vl;
        }
    } else {
#pragma unroll
        for (int a = 0; a < 4; a++) {
            int row0 = mBase + wr * 64 + a * 16 + (lane >> 2);
#pragma unroll
            for (int n = 0; n < 4; n++) {
                int col = nBase + wc * 32 + n * 8 + (lane & 3) * 2;
                *(float2*)&C[(size_t)row0 * N + col]       = make_float2(acc[a][n][0], acc[a][n][1]);
                *(float2*)&C[(size_t)(row0 + 8) * N + col] = make_float2(acc[a][n][2], acc[a][n][3]);
            }
        }
    }
}

// ---------------------------------------------------------------------------
// Tensor-core causal flash attention (R13 + causal tile-skip on diagonal).
// KB=128 K-tiles, 2 x 64KB cp.async stages, occupancy 1. Q from g_kv.
// Stage layout (bytes): Khi@0, Klo@16K, Vhi@32K, Vlo@48K. XOR swizzle.
// ---------------------------------------------------------------------------
__device__ __forceinline__ void attn_prefetch(uint32_t dstbase, size_t bhoff,
                                              int krow0, int tid)
{
#pragma unroll
    for (int j = 0; j < 16; j++) {
        int c = tid + j * 256;            // 0..4095
        int m = c >> 10;                  // 0..3 -> mats 2..5 (Khi,Klo,Vhi,Vlo)
        int w = c & 1023;
        int r = w >> 3, sg = w & 7;
        uint32_t off = (uint32_t)(m * 16384) +
                       (uint32_t)(r * 64 + ((sg ^ (r & 7)) * 8)) * 2;
        cp16(dstbase + off,
             g_kv + (size_t)(m + 2) * KV_MS + bhoff + (size_t)(krow0 + r) * DK + sg * 8);
    }
}

__global__ void __launch_bounds__(256, 1) attn_tc(__nv_bfloat16* __restrict__ atte)
{
    extern __shared__ __nv_bfloat16 sm[];
    const uint32_t sbase = (uint32_t)__cvta_generic_to_shared(sm);

    const int b = blockIdx.z, h = blockIdx.y;
    const int qt = (int)(gridDim.x - 1 - blockIdx.x);   // heavy tiles first
    const int q0 = qt * 128;
    const int tid = threadIdx.x;
    const int lane = tid & 31, warp = tid >> 5;

    const size_t bhoff = ((size_t)(b * NHEADS + h)) * SEQ * DK;

    // --- Stage Q (pre-scaled) into stage0: Qhi@[0,16KB), Qlo@[16KB,32KB)
#pragma unroll
    for (int j = 0; j < 8; j++) {
        int c = tid + j * 256;
        int m = c >> 10;                  // 0=Qhi,1=Qlo
        int w = c & 1023;
        int r = w >> 3, sg = w & 7;
        uint32_t off = (uint32_t)(m * 16384) +
                       (uint32_t)(r * 64 + ((sg ^ (r & 7)) * 8)) * 2;
        cp16(sbase + off,
             g_kv + (size_t)m * KV_MS + bhoff + (size_t)(q0 + r) * DK + sg * 8);
    }
    asm volatile("cp.async.commit_group;");
    // overlap: prefetch tile 0 -> stage 1 before waiting on Q
    attn_prefetch(sbase + 65536, bhoff, 0, tid);
    asm volatile("cp.async.commit_group;");
    asm volatile("cp.async.wait_group 1;");
    __syncthreads();

    // --- Q fragments into registers
    uint32_t qh[4][4], ql[4][4];
    {
        const int r = warp * 16 + (lane & 15);
        const int sgx = lane >> 4;
#pragma unroll
        for (int ks = 0; ks < 4; ks++) {
            int sg = (2 * ks + sgx) ^ (r & 7);
            uint32_t ad = sbase + (uint32_t)(r * 64 + sg * 8) * 2;
            ldm_x4(qh[ks][0], qh[ks][1], qh[ks][2], qh[ks][3], ad);
            ldm_x4(ql[ks][0], ql[ks][1], ql[ks][2], ql[ks][3], ad + 16384);
        }
    }
    __syncthreads();   // stage0 free

    float o[8][4];
#pragma unroll
    for (int t = 0; t < 8; t++) { o[t][0]=0.f; o[t][1]=0.f; o[t][2]=0.f; o[t][3]=0.f; }
    float m0 = -1e30f, m1 = -1e30f, l0 = 0.f, l1 = 0.f;

    for (int kt = 0; kt <= qt; kt++) {
        const int kbase = kt * 128;
        const bool diag = (kt == qt);
        if (kt + 1 <= qt) {
            attn_prefetch(sbase + (uint32_t)(kt & 1) * 65536, bhoff, kbase + 128, tid);
            asm volatile("cp.async.commit_group;");
            asm volatile("cp.async.wait_group 1;");
        } else {
            asm volatile("cp.async.wait_group 0;");
        }
        __syncthreads();
        const uint32_t sstage = sbase + (uint32_t)((kt + 1) & 1) * 65536;

        // ---- S = Q K^T (3-term split), 128 keys
        float s[16][4];
#pragma unroll
        for (int t = 0; t < 16; t++) { s[t][0]=0.f; s[t][1]=0.f; s[t][2]=0.f; s[t][3]=0.f; }

#pragma unroll
        for (int kk = 0; kk < 4; kk++) {
#pragma unroll
            for (int np = 0; np < 8; np++) {
                // causal skip: on the diagonal tile, np-tiles beyond the warp's
                // rows are fully masked -> skip their ldm+mma entirely.
                if (diag && np > warp) continue;
                int krow = np * 16 + (lane & 7) + (((lane >> 4) & 1) << 3);
                int ksg = (2 * kk + ((lane >> 3) & 1)) ^ (krow & 7);
                uint32_t ad = sstage + (uint32_t)(krow * 64 + ksg * 8) * 2;
                uint32_t bh0, bh1, bh2, bh3, bl0, bl1, bl2, bl3;
                ldm_x4(bh0, bh1, bh2, bh3, ad);
                ldm_x4(bl0, bl1, bl2, bl3, ad + 16384);
                uint32_t bb[2];
                bb[0] = bh0; bb[1] = bh1;
                mma16816(s[2*np],   qh[kk], bb);
                mma16816(s[2*np],   ql[kk], bb);
                bb[0] = bh2; bb[1] = bh3;
                mma16816(s[2*np+1], qh[kk], bb);
                mma16816(s[2*np+1], ql[kk], bb);
                bb[0] = bl0; bb[1] = bl1;
                mma16816(s[2*np],   qh[kk], bb);
                bb[0] = bl2; bb[1] = bl3;
                mma16816(s[2*np+1], qh[kk], bb);
            }
        }

        // ---- causal mask on the diagonal tile
        const int rg0 = q0 + warp * 16 + (lane >> 2);
        if (diag) {
#pragma unroll
            for (int nt = 0; nt < 16; nt++) {
                int c0 = kbase + nt * 8 + 2 * (lane & 3);
                if (c0     > rg0)     s[nt][0] = -1e30f;
                if (c0 + 1 > rg0)     s[nt][1] = -1e30f;
                if (c0     > rg0 + 8) s[nt][2] = -1e30f;
                if (c0 + 1 > rg0 + 8) s[nt][3] = -1e30f;
            }
        }

        // ---- online softmax (rows rg0, rg0+8)
        float mx0 = -1e30f, mx1 = -1e30f;
#pragma unroll
        for (int nt = 0; nt < 16; nt++) {
            mx0 = fmaxf(mx0, fmaxf(s[nt][0], s[nt][1]));
            mx1 = fmaxf(mx1, fmaxf(s[nt][2], s[nt][3]));
        }
        mx0 = fmaxf(mx0, __shfl_xor_sync(0xffffffffu, mx0, 1));
        mx0 = fmaxf(mx0, __shfl_xor_sync(0xffffffffu, mx0, 2));
        mx1 = fmaxf(mx1, __shfl_xor_sync(0xffffffffu, mx1, 1));
        mx1 = fmaxf(mx1, __shfl_xor_sync(0xffffffffu, mx1, 2));
        float mn0 = fmaxf(m0, mx0), mn1 = fmaxf(m1, mx1);
        float cr0 = __expf(m0 - mn0), cr1 = __expf(m1 - mn1);
        m0 = mn0; m1 = mn1;
        float sum0 = 0.f, sum1 = 0.f;
#pragma unroll
        for (int nt = 0; nt < 16; nt++) {
            s[nt][0] = __expf(s[nt][0] - mn0);
            s[nt][1] = __expf(s[nt][1] - mn0);
            s[nt][2] = __expf(s[nt][2] - mn1);
            s[nt][3] = __expf(s[nt][3] - mn1);
            sum0 += s[nt][0] + s[nt][1];
            sum1 += s[nt][2] + s[nt][3];
        }
        sum0 += __shfl_xor_sync(0xffffffffu, sum0, 1);
        sum0 += __shfl_xor_sync(0xffffffffu, sum0, 2);
        sum1 += __shfl_xor_sync(0xffffffffu, sum1, 1);
        sum1 += __shfl_xor_sync(0xffffffffu, sum1, 2);
        l0 = l0 * cr0 + sum0;
        l1 = l1 * cr1 + sum1;
#pragma unroll
        for (int t = 0; t < 8; t++) {
            o[t][0] *= cr0; o[t][1] *= cr0; o[t][2] *= cr1; o[t][3] *= cr1;
        }

        // ---- O += P V (3-term split), V tile 128 rows
#pragma unroll
        for (int ks = 0; ks < 8; ks++) {
            // causal skip: on the diagonal tile, ks-tiles beyond the warp's rows
            // have P == 0 -> their PV contribution is exactly zero.
            if (diag && ks > warp) continue;
            uint32_t ah[4], al[4];
            pack_hilo(s[2*ks][0],   s[2*ks][1],   ah[0], al[0]);
            pack_hilo(s[2*ks][2],   s[2*ks][3],   ah[1], al[1]);
            pack_hilo(s[2*ks+1][0], s[2*ks+1][1], ah[2], al[2]);
            pack_hilo(s[2*ks+1][2], s[2*ks+1][3], ah[3], al[3]);
#pragma unroll
            for (int cp = 0; cp < 4; cp++) {
                int vrow = ks * 16 + (lane & 15);
                int vsg = (2 * cp + (lane >> 4)) ^ (vrow & 7);
                uint32_t va = sstage + 32768 + (uint32_t)(vrow * 64 + vsg * 8) * 2;
                uint32_t vh0, vh1, vh2, vh3, vl0, vl1, vl2, vl3;
                ldm_x4_t(vh0, vh1, vh2, vh3, va);
                ldm_x4_t(vl0, vl1, vl2, vl3, va + 16384);
                uint32_t bb[2];
                bb[0] = vh0; bb[1] = vh1;
                mma16816(o[2*cp],   ah, bb);
                mma16816(o[2*cp],   al, bb);
                bb[0] = vl0; bb[1] = vl1;
                mma16816(o[2*cp],   ah, bb);
                bb[0] = vh2; bb[1] = vh3;
                mma16816(o[2*cp+1], ah, bb);
                mma16816(o[2*cp+1], al, bb);
                bb[0] = vl2; bb[1] = vl3;
                mma16816(o[2*cp+1], ah, bb);
            }
        }
        __syncthreads();   // done reading this stage
    }

    // ---- epilogue: write [hi|lo] 2K layout
    const float inv0 = 1.f / l0, inv1 = 1.f / l1;
    const int rg0 = q0 + warp * 16 + (lane >> 2);
    const size_t ro0 = (size_t)(b * SEQ + rg0) * KE2;
    const size_t ro1 = (size_t)(b * SEQ + rg0 + 8) * KE2;
#pragma unroll
    for (int nt = 0; nt < 8; nt++) {
        int col = h * DK + nt * 8 + 2 * (lane & 3);
        uint32_t hi, lo;
        pack_hilo(o[nt][0] * inv0, o[nt][1] * inv0, hi, lo);
        *(uint32_t*)(atte + ro0 + col)          = hi;
        *(uint32_t*)(atte + ro0 + DMODEL + col) = lo;
        pack_hilo(o[nt][2] * inv1, o[nt][3] * inv1, hi, lo);
        *(uint32_t*)(atte + ro1 + col)          = hi;
        *(uint32_t*)(atte + ro1 + DMODEL + col) = lo;
    }
}

// ---------------------------------------------------------------------------
// kernel_launch
// ---------------------------------------------------------------------------
extern "C" void kernel_launch(void* const* d_in, const int* in_sizes, int n_in,
                              void* d_out, int out_size)
{
    const float* x     = (const float*)d_in[0];   // [2, 2048, 1024]
    const float* W_qkv = (const float*)d_in[1];   // [3072, 1024]
    const float* W_out = (const float*)d_in[2];   // [1024, 1024]
    float* out = (float*)d_out;                   // [2, 2048, 1024]

    __nv_bfloat16 *xe, *wqkve, *wute, *atte;
    cudaGetSymbolAddress((void**)&xe,    g_xe);
    cudaGetSymbolAddress((void**)&wqkve, g_wqkve);
    cudaGetSymbolAddress((void**)&wute,  g_wute);
    cudaGetSymbolAddress((void**)&atte,  g_atte);

    cudaFuncSetAttribute(gemm_bf16<0>, cudaFuncAttributeMaxDynamicSharedMemorySize, 3 * GSTAGE_BYTES);
    cudaFuncSetAttribute(gemm_bf16<1>, cudaFuncAttributeMaxDynamicSharedMemorySize, 3 * GSTAGE_BYTES);
    cudaFuncSetAttribute(attn_tc,      cudaFuncAttributeMaxDynamicSharedMemorySize, 131072);

    // 0) split conversions (inputs) -> [hi|lo] 2K layout
    {
        size_t tx_ = (size_t)MTOT * DMODEL;
        conv_split<<<(unsigned)((tx_/4 + 255)/256), 256>>>(x, xe, DMODEL, tx_);
        size_t tw = (size_t)QKV_N * DMODEL;
        conv_split<<<(unsigned)((tw/4 + 255)/256), 256>>>(W_qkv, wqkve, DMODEL, tw);
        size_t tu = (size_t)DMODEL * DMODEL;
        conv_split<<<(unsigned)((tu/4 + 255)/256), 256>>>(W_out, wute, DMODEL, tu);
    }
    // 1) QKV projection fused: writes Qhi/Qlo (scaled), Khi/Klo, Vhi/Vlo into g_kv
    {
        dim3 grid(QKV_N / 128, MTOT / 128);
        gemm_bf16<1><<<grid, 256, 3 * GSTAGE_BYTES>>>(xe, wqkve, nullptr, QKV_N);
    }
    // 2) tensor-core causal flash attention -> g_atte ([hi|lo] layout)
    {
        dim3 grid(SEQ / 128, NHEADS, BATCH);
        attn_tc<<<grid, 256, 131072>>>(atte);
    }
    // 3) output projection -> d_out
    {
        dim3 grid(DMODEL / 128, MTOT / 128);
        gemm_bf16<0><<<grid, 256, 3 * GSTAGE_BYTES>>>(atte, wute, out, DMODEL);
    }
}

// round 15
// speedup vs baseline: 1.1154x; 1.1154x over previous
#include <cuda_runtime.h>
#include <cuda_bf16.h>
#include <math.h>
#include <stdint.h>

// Problem constants
#define BATCH 2
#define SEQ   2048
#define DMODEL 1024
#define NHEADS 16
#define DK    64
#define MTOT  (BATCH*SEQ)          // 4096
#define QKV_N (3*DMODEL)           // 3072
#define KE2   (2*DMODEL)           // 2048: [hi | lo] layout width
#define KV_MS ((size_t)MTOT * DMODEL)   // per-matrix stride in g_kv

// Scratch (device globals — no allocation allowed)
__device__ __nv_bfloat16 g_xe   [(size_t)MTOT  * KE2];    // x      [hi|lo]
__device__ __nv_bfloat16 g_wqkve[(size_t)QKV_N * KE2];    // W_qkv  [hi|lo]
__device__ __nv_bfloat16 g_wute [(size_t)DMODEL* KE2];    // W_out  [hi|lo]
__device__ __nv_bfloat16 g_atte [(size_t)MTOT  * KE2];    // attn out [hi|lo]
// fused qkv output: [m][b*h][s][dk], m = {Qhi,Qlo,Khi,Klo,Vhi,Vlo} (Q pre-scaled)
__device__ __nv_bfloat16 g_kv[(size_t)6 * MTOT * DMODEL];

// ---------------------------------------------------------------------------
// helpers
// ---------------------------------------------------------------------------
__device__ __forceinline__ void pack_hilo(float a, float b, uint32_t& hi, uint32_t& lo)
{
    __nv_bfloat16 ha = __float2bfloat16_rn(a), hb = __float2bfloat16_rn(b);
    __nv_bfloat162 h; h.x = ha; h.y = hb;
    __nv_bfloat162 l;
    l.x = __float2bfloat16_rn(a - __bfloat162float(ha));
    l.y = __float2bfloat16_rn(b - __bfloat162float(hb));
    hi = *(uint32_t*)&h; lo = *(uint32_t*)&l;
}

__device__ __forceinline__ void ldm_x4(uint32_t& r0, uint32_t& r1, uint32_t& r2, uint32_t& r3,
                                       uint32_t addr)
{
    asm volatile("ldmatrix.sync.aligned.m8n8.x4.shared.b16 {%0,%1,%2,%3}, [%4];"
                 : "=r"(r0), "=r"(r1), "=r"(r2), "=r"(r3) : "r"(addr));
}

__device__ __forceinline__ void ldm_x4_t(uint32_t& r0, uint32_t& r1, uint32_t& r2, uint32_t& r3,
                                         uint32_t addr)
{
    asm volatile("ldmatrix.sync.aligned.m8n8.x4.trans.shared.b16 {%0,%1,%2,%3}, [%4];"
                 : "=r"(r0), "=r"(r1), "=r"(r2), "=r"(r3) : "r"(addr));
}

__device__ __forceinline__ void mma16816(float* d, const uint32_t* a, const uint32_t* b)
{
    asm volatile(
        "mma.sync.aligned.m16n8k16.row.col.f32.bf16.bf16.f32 "
        "{%0,%1,%2,%3}, {%4,%5,%6,%7}, {%8,%9}, {%0,%1,%2,%3};"
        : "+f"(d[0]), "+f"(d[1]), "+f"(d[2]), "+f"(d[3])
        : "r"(a[0]), "r"(a[1]), "r"(a[2]), "r"(a[3]), "r"(b[0]), "r"(b[1]));
}

__device__ __forceinline__ void cp16(uint32_t saddr, const void* gptr)
{
    asm volatile("cp.async.cg.shared.global [%0], [%1], 16;" :: "r"(saddr), "l"(gptr));
}

// ---------------------------------------------------------------------------
// Split-conversion: f32 [R,K] -> bf16 [R,2K]  ([k]=hi, [K+k]=lo)
// ---------------------------------------------------------------------------
__global__ void conv_split(const float* __restrict__ in, __nv_bfloat16* __restrict__ out,
                           int K, size_t total)
{
    size_t idx = ((size_t)blockIdx.x * blockDim.x + threadIdx.x) * 4;
    if (idx >= total) return;
    int r = (int)(idx / K);
    int k = (int)(idx % K);
    float4 v = *(const float4*)(in + idx);
    uint32_t hi01, hi23, lo01, lo23;
    pack_hilo(v.x, v.y, hi01, lo01);
    pack_hilo(v.z, v.w, hi23, lo23);
    __nv_bfloat16* o = out + (size_t)r * (2 * K) + k;
    *(uint32_t*)(o + 0) = hi01;  *(uint32_t*)(o + 2) = hi23;
    *(uint32_t*)(o + K + 0) = lo01; *(uint32_t*)(o + K + 2) = lo23;
}

// ---------------------------------------------------------------------------
// bf16 tensor-core GEMM with 3-term fragment reuse (frozen from R13):
//   C = Ahi*Bhi^T + Alo*Bhi^T + Ahi*Blo^T   (fp32 accumulate)
// ---------------------------------------------------------------------------
#define GSTAGE_BYTES 32768

template<int FUSE>
__global__ void __launch_bounds__(256, 2) gemm_bf16(
    const __nv_bfloat16* __restrict__ A, const __nv_bfloat16* __restrict__ B,
    float* __restrict__ C, int N)
{
    extern __shared__ __nv_bfloat16 gsm[];
    const uint32_t sbase = (uint32_t)__cvta_generic_to_shared(gsm);

    const int tid  = threadIdx.x;
    const int lane = tid & 31;
    const int warp = tid >> 5;
    const int wr = warp >> 2;
    const int wc = warp & 3;
    const int mBase = blockIdx.y * 128;
    const int nBase = blockIdx.x * 128;

    const int lrow = tid >> 2;
    const int lseg = tid & 3;
    const uint32_t swz0 = (uint32_t)(lrow * 32 + ((lseg ^ ((lrow >> 1) & 3)) * 8)) * 2;
    const uint32_t swz1 = (uint32_t)((lrow + 64) * 32 + ((lseg ^ (((lrow + 64) >> 1) & 3)) * 8)) * 2;
    const __nv_bfloat16* gA0 = A + (size_t)(mBase + lrow)      * KE2 + lseg * 8;
    const __nv_bfloat16* gA1 = A + (size_t)(mBase + lrow + 64) * KE2 + lseg * 8;
    const __nv_bfloat16* gB0 = B + (size_t)(nBase + lrow)      * KE2 + lseg * 8;
    const __nv_bfloat16* gB1 = B + (size_t)(nBase + lrow + 64) * KE2 + lseg * 8;

    const int arow = wr * 64 + (lane & 15);
    const int aseg = (lane >> 4) & 1;
    const int brow = wc * 32 + (lane & 7) + (((lane >> 4) & 1) << 3);
    const int bseg = (lane >> 3) & 1;

    float acc[4][4][4];
#pragma unroll
    for (int a = 0; a < 4; a++)
#pragma unroll
        for (int n = 0; n < 4; n++)
#pragma unroll
            for (int i = 0; i < 4; i++) acc[a][n][i] = 0.f;

    const int NSTEP = DMODEL / 32;     // 32 real-K steps

#pragma unroll
    for (int s = 0; s < 2; s++) {
        const uint32_t st = sbase + s * GSTAGE_BYTES;
        const int k0 = s * 32;
        cp16(st +          swz0, gA0 + k0);           cp16(st +          swz1, gA1 + k0);
        cp16(st +  8192 + swz0, gA0 + DMODEL + k0);   cp16(st +  8192 + swz1, gA1 + DMODEL + k0);
        cp16(st + 16384 + swz0, gB0 + k0);            cp16(st + 16384 + swz1, gB1 + k0);
        cp16(st + 24576 + swz0, gB0 + DMODEL + k0);   cp16(st + 24576 + swz1, gB1 + DMODEL + k0);
        asm volatile("cp.async.commit_group;");
    }

    int cur = 0, nxt = 2;
    for (int t = 0; t < NSTEP; t++) {
        if (t + 1 < NSTEP) asm volatile("cp.async.wait_group 1;");
        else               asm volatile("cp.async.wait_group 0;");
        __syncthreads();

        if (t + 2 < NSTEP) {
            const uint32_t st = sbase + nxt * GSTAGE_BYTES;
            const int k0 = (t + 2) * 32;
            cp16(st +          swz0, gA0 + k0);           cp16(st +          swz1, gA1 + k0);
            cp16(st +  8192 + swz0, gA0 + DMODEL + k0);   cp16(st +  8192 + swz1, gA1 + DMODEL + k0);
            cp16(st + 16384 + swz0, gB0 + k0);            cp16(st + 16384 + swz1, gB1 + k0);
            cp16(st + 24576 + swz0, gB0 + DMODEL + k0);   cp16(st + 24576 + swz1, gB1 + DMODEL + k0);
            asm volatile("cp.async.commit_group;");
        }

        const uint32_t stg = sbase + cur * GSTAGE_BYTES;

#pragma unroll
        for (int kk = 0; kk < 2; kk++) {
            uint32_t ah[4][4];
#pragma unroll
            for (int a = 0; a < 4; a++) {
                int r = arow + a * 16;
                int seg = (kk * 2 + aseg) ^ ((r >> 1) & 3);
                ldm_x4(ah[a][0], ah[a][1], ah[a][2], ah[a][3],
                       stg + (uint32_t)(r * 32 + seg * 8) * 2);
            }
            uint32_t bh[4][2];
#pragma unroll
            for (int p = 0; p < 2; p++) {
                int n = brow + p * 16;
                int seg = (kk * 2 + bseg) ^ ((n >> 1) & 3);
                uint32_t r0, r1, r2, r3;
                ldm_x4(r0, r1, r2, r3, stg + 16384 + (uint32_t)(n * 32 + seg * 8) * 2);
                bh[p * 2 + 0][0] = r0; bh[p * 2 + 0][1] = r1;
                bh[p * 2 + 1][0] = r2; bh[p * 2 + 1][1] = r3;
            }
#pragma unroll
            for (int a = 0; a < 4; a++)
#pragma unroll
                for (int n = 0; n < 4; n++)
                    mma16816(acc[a][n], ah[a], bh[n]);

            {
                uint32_t al[4][4];
#pragma unroll
                for (int a = 0; a < 4; a++) {
                    int r = arow + a * 16;
                    int seg = (kk * 2 + aseg) ^ ((r >> 1) & 3);
                    ldm_x4(al[a][0], al[a][1], al[a][2], al[a][3],
                           stg + 8192 + (uint32_t)(r * 32 + seg * 8) * 2);
                }
#pragma unroll
                for (int a = 0; a < 4; a++)
#pragma unroll
                    for (int n = 0; n < 4; n++)
                        mma16816(acc[a][n], al[a], bh[n]);
            }
            {
                uint32_t bl[4][2];
#pragma unroll
                for (int p = 0; p < 2; p++) {
                    int n = brow + p * 16;
                    int seg = (kk * 2 + bseg) ^ ((n >> 1) & 3);
                    uint32_t r0, r1, r2, r3;
                    ldm_x4(r0, r1, r2, r3, stg + 24576 + (uint32_t)(n * 32 + seg * 8) * 2);
                    bl[p * 2 + 0][0] = r0; bl[p * 2 + 0][1] = r1;
                    bl[p * 2 + 1][0] = r2; bl[p * 2 + 1][1] = r3;
                }
#pragma unroll
                for (int a = 0; a < 4; a++)
#pragma unroll
                    for (int n = 0; n < 4; n++)
                        mma16816(acc[a][n], ah[a], bl[n]);
            }
        }
        cur = (cur == 2) ? 0 : cur + 1;
        nxt = (nxt == 2) ? 0 : nxt + 1;
    }

    if (FUSE) {
        __syncthreads();
        const int region = nBase >> 10;                // 0=Q,1=K,2=V
        const int colbase = nBase & 1023;
        const float scale = (region == 0) ? 0.125f : 1.0f;
        char* smc = (char*)gsm;

#pragma unroll
        for (int a = 0; a < 4; a++) {
            int r0_ = wr * 64 + a * 16 + (lane >> 2);
#pragma unroll
            for (int n = 0; n < 4; n++) {
                int lcol = wc * 32 + n * 8 + (lane & 3) * 2;
                int chunk = lcol >> 3;
                int inb   = (lcol * 2) & 15;
                uint32_t hi, lo;
                pack_hilo(acc[a][n][0] * scale, acc[a][n][1] * scale, hi, lo);
                {
                    uint32_t byte = (uint32_t)r0_ * 256 + (((chunk ^ (r0_ & 7)) << 4) + inb);
                    *(uint32_t*)(smc + byte)         = hi;
                    *(uint32_t*)(smc + 32768 + byte) = lo;
                }
                pack_hilo(acc[a][n][2] * scale, acc[a][n][3] * scale, hi, lo);
                {
                    int r1_ = r0_ + 8;
                    uint32_t byte = (uint32_t)r1_ * 256 + (((chunk ^ (r1_ & 7)) << 4) + inb);
                    *(uint32_t*)(smc + byte)         = hi;
                    *(uint32_t*)(smc + 32768 + byte) = lo;
                }
            }
        }
        __syncthreads();

        __nv_bfloat16* mhi = g_kv + (size_t)(2 * region)     * KV_MS;
        __nv_bfloat16* mlo = g_kv + (size_t)(2 * region + 1) * KV_MS;
#pragma unroll
        for (int j = 0; j < 8; j++) {
            int it = tid + j * 256;
            int r_ = it >> 4;
            int ch = it & 15;
            uint32_t byte = (uint32_t)r_ * 256 + ((ch ^ (r_ & 7)) << 4);
            uint4 vh = *(uint4*)(smc + byte);
            uint4 vl = *(uint4*)(smc + 32768 + byte);
            int grow = mBase + r_;
            int col = colbase + ch * 8;
            int hh = col >> 6, dd = col & 63;
            int bb_ = grow >> 11, ss = grow & 2047;
            size_t dst = (((size_t)(bb_ * NHEADS + hh)) * SEQ + ss) * DK + dd;
            *(uint4*)&mhi[dst] = vh;
            *(uint4*)&mlo[dst] = vl;
        }
    } else {
#pragma unroll
        for (int a = 0; a < 4; a++) {
            int row0 = mBase + wr * 64 + a * 16 + (lane >> 2);
#pragma unroll
            for (int n = 0; n < 4; n++) {
                int col = nBase + wc * 32 + n * 8 + (lane & 3) * 2;
                *(float2*)&C[(size_t)row0 * N + col]       = make_float2(acc[a][n][0], acc[a][n][1]);
                *(float2*)&C[(size_t)(row0 + 8) * N + col] = make_float2(acc[a][n][2], acc[a][n][3]);
            }
        }
    }
}

// ---------------------------------------------------------------------------
// Tensor-core causal flash attention: R13 branch-free mainloop over
// non-diagonal tiles + PEELED diagonal tile with triangular warp bounds.
// KB=128 K-tiles, 2 x 64KB cp.async stages, occupancy 1. Q from g_kv.
// Stage layout (bytes): Khi@0, Klo@16K, Vhi@32K, Vlo@48K. XOR swizzle.
// ---------------------------------------------------------------------------
__device__ __forceinline__ void attn_prefetch(uint32_t dstbase, size_t bhoff,
                                              int krow0, int tid)
{
#pragma unroll
    for (int j = 0; j < 16; j++) {
        int c = tid + j * 256;            // 0..4095
        int m = c >> 10;                  // 0..3 -> mats 2..5 (Khi,Klo,Vhi,Vlo)
        int w = c & 1023;
        int r = w >> 3, sg = w & 7;
        uint32_t off = (uint32_t)(m * 16384) +
                       (uint32_t)(r * 64 + ((sg ^ (r & 7)) * 8)) * 2;
        cp16(dstbase + off,
             g_kv + (size_t)(m + 2) * KV_MS + bhoff + (size_t)(krow0 + r) * DK + sg * 8);
    }
}

__global__ void __launch_bounds__(256, 1) attn_tc(__nv_bfloat16* __restrict__ atte)
{
    extern __shared__ __nv_bfloat16 sm[];
    const uint32_t sbase = (uint32_t)__cvta_generic_to_shared(sm);

    const int b = blockIdx.z, h = blockIdx.y;
    const int qt = (int)(gridDim.x - 1 - blockIdx.x);   // heavy tiles first
    const int q0 = qt * 128;
    const int tid = threadIdx.x;
    const int lane = tid & 31, warp = tid >> 5;

    const size_t bhoff = ((size_t)(b * NHEADS + h)) * SEQ * DK;

    // --- Stage Q (pre-scaled) into stage0: Qhi@[0,16KB), Qlo@[16KB,32KB)
#pragma unroll
    for (int j = 0; j < 8; j++) {
        int c = tid + j * 256;
        int m = c >> 10;                  // 0=Qhi,1=Qlo
        int w = c & 1023;
        int r = w >> 3, sg = w & 7;
        uint32_t off = (uint32_t)(m * 16384) +
                       (uint32_t)(r * 64 + ((sg ^ (r & 7)) * 8)) * 2;
        cp16(sbase + off,
             g_kv + (size_t)m * KV_MS + bhoff + (size_t)(q0 + r) * DK + sg * 8);
    }
    asm volatile("cp.async.commit_group;");
    // overlap: prefetch tile 0 -> stage 1 before waiting on Q
    attn_prefetch(sbase + 65536, bhoff, 0, tid);
    asm volatile("cp.async.commit_group;");
    asm volatile("cp.async.wait_group 1;");
    __syncthreads();

    // --- Q fragments into registers
    uint32_t qh[4][4], ql[4][4];
    {
        const int r = warp * 16 + (lane & 15);
        const int sgx = lane >> 4;
#pragma unroll
        for (int ks = 0; ks < 4; ks++) {
            int sg = (2 * ks + sgx) ^ (r & 7);
            uint32_t ad = sbase + (uint32_t)(r * 64 + sg * 8) * 2;
            ldm_x4(qh[ks][0], qh[ks][1], qh[ks][2], qh[ks][3], ad);
            ldm_x4(ql[ks][0], ql[ks][1], ql[ks][2], ql[ks][3], ad + 16384);
        }
    }
    __syncthreads();   // stage0 free

    float o[8][4];
#pragma unroll
    for (int t = 0; t < 8; t++) { o[t][0]=0.f; o[t][1]=0.f; o[t][2]=0.f; o[t][3]=0.f; }
    float m0 = -1e30f, m1 = -1e30f, l0 = 0.f, l1 = 0.f;

    // ===== main loop: non-diagonal tiles, branch-free (exact R13 body, no mask)
    for (int kt = 0; kt < qt; kt++) {
        const int kbase = kt * 128;
        attn_prefetch(sbase + (uint32_t)(kt & 1) * 65536, bhoff, kbase + 128, tid);
        asm volatile("cp.async.commit_group;");
        asm volatile("cp.async.wait_group 1;");
        __syncthreads();
        const uint32_t sstage = sbase + (uint32_t)((kt + 1) & 1) * 65536;

        float s[16][4];
#pragma unroll
        for (int t = 0; t < 16; t++) { s[t][0]=0.f; s[t][1]=0.f; s[t][2]=0.f; s[t][3]=0.f; }

#pragma unroll
        for (int kk = 0; kk < 4; kk++) {
#pragma unroll
            for (int np = 0; np < 8; np++) {
                int krow = np * 16 + (lane & 7) + (((lane >> 4) & 1) << 3);
                int ksg = (2 * kk + ((lane >> 3) & 1)) ^ (krow & 7);
                uint32_t ad = sstage + (uint32_t)(krow * 64 + ksg * 8) * 2;
                uint32_t bh0, bh1, bh2, bh3, bl0, bl1, bl2, bl3;
                ldm_x4(bh0, bh1, bh2, bh3, ad);
                ldm_x4(bl0, bl1, bl2, bl3, ad + 16384);
                uint32_t bb[2];
                bb[0] = bh0; bb[1] = bh1;
                mma16816(s[2*np],   qh[kk], bb);
                mma16816(s[2*np],   ql[kk], bb);
                bb[0] = bh2; bb[1] = bh3;
                mma16816(s[2*np+1], qh[kk], bb);
                mma16816(s[2*np+1], ql[kk], bb);
                bb[0] = bl0; bb[1] = bl1;
                mma16816(s[2*np],   qh[kk], bb);
                bb[0] = bl2; bb[1] = bl3;
                mma16816(s[2*np+1], qh[kk], bb);
            }
        }

        float mx0 = -1e30f, mx1 = -1e30f;
#pragma unroll
        for (int nt = 0; nt < 16; nt++) {
            mx0 = fmaxf(mx0, fmaxf(s[nt][0], s[nt][1]));
            mx1 = fmaxf(mx1, fmaxf(s[nt][2], s[nt][3]));
        }
        mx0 = fmaxf(mx0, __shfl_xor_sync(0xffffffffu, mx0, 1));
        mx0 = fmaxf(mx0, __shfl_xor_sync(0xffffffffu, mx0, 2));
        mx1 = fmaxf(mx1, __shfl_xor_sync(0xffffffffu, mx1, 1));
        mx1 = fmaxf(mx1, __shfl_xor_sync(0xffffffffu, mx1, 2));
        float mn0 = fmaxf(m0, mx0), mn1 = fmaxf(m1, mx1);
        float cr0 = __expf(m0 - mn0), cr1 = __expf(m1 - mn1);
        m0 = mn0; m1 = mn1;
        float sum0 = 0.f, sum1 = 0.f;
#pragma unroll
        for (int nt = 0; nt < 16; nt++) {
            s[nt][0] = __expf(s[nt][0] - mn0);
            s[nt][1] = __expf(s[nt][1] - mn0);
            s[nt][2] = __expf(s[nt][2] - mn1);
            s[nt][3] = __expf(s[nt][3] - mn1);
            sum0 += s[nt][0] + s[nt][1];
            sum1 += s[nt][2] + s[nt][3];
        }
        sum0 += __shfl_xor_sync(0xffffffffu, sum0, 1);
        sum0 += __shfl_xor_sync(0xffffffffu, sum0, 2);
        sum1 += __shfl_xor_sync(0xffffffffu, sum1, 1);
        sum1 += __shfl_xor_sync(0xffffffffu, sum1, 2);
        l0 = l0 * cr0 + sum0;
        l1 = l1 * cr1 + sum1;
#pragma unroll
        for (int t = 0; t < 8; t++) {
            o[t][0] *= cr0; o[t][1] *= cr0; o[t][2] *= cr1; o[t][3] *= cr1;
        }

#pragma unroll
        for (int ks = 0; ks < 8; ks++) {
            uint32_t ah[4], al[4];
            pack_hilo(s[2*ks][0],   s[2*ks][1],   ah[0], al[0]);
            pack_hilo(s[2*ks][2],   s[2*ks][3],   ah[1], al[1]);
            pack_hilo(s[2*ks+1][0], s[2*ks+1][1], ah[2], al[2]);
            pack_hilo(s[2*ks+1][2], s[2*ks+1][3], ah[3], al[3]);
#pragma unroll
            for (int cp = 0; cp < 4; cp++) {
                int vrow = ks * 16 + (lane & 15);
                int vsg = (2 * cp + (lane >> 4)) ^ (vrow & 7);
                uint32_t va = sstage + 32768 + (uint32_t)(vrow * 64 + vsg * 8) * 2;
                uint32_t vh0, vh1, vh2, vh3, vl0, vl1, vl2, vl3;
                ldm_x4_t(vh0, vh1, vh2, vh3, va);
                ldm_x4_t(vl0, vl1, vl2, vl3, va + 16384);
                uint32_t bb[2];
                bb[0] = vh0; bb[1] = vh1;
                mma16816(o[2*cp],   ah, bb);
                mma16816(o[2*cp],   al, bb);
                bb[0] = vl0; bb[1] = vl1;
                mma16816(o[2*cp],   ah, bb);
                bb[0] = vh2; bb[1] = vh3;
                mma16816(o[2*cp+1], ah, bb);
                mma16816(o[2*cp+1], al, bb);
                bb[0] = vl2; bb[1] = vl3;
                mma16816(o[2*cp+1], ah, bb);
            }
        }
        __syncthreads();
    }

    // ===== peeled diagonal tile (kt == qt): triangular warp bounds + mask
    {
        const int kbase = qt * 128;
        asm volatile("cp.async.wait_group 0;");
        __syncthreads();
        const uint32_t sstage = sbase + (uint32_t)((qt + 1) & 1) * 65536;

        float s[16][4];
#pragma unroll
        for (int t = 0; t < 16; t++) { s[t][0]=0.f; s[t][1]=0.f; s[t][2]=0.f; s[t][3]=0.f; }

        // S: only np-tiles <= warp carry unmasked entries
        for (int np = 0; np <= warp; np++) {
            int krow = np * 16 + (lane & 7) + (((lane >> 4) & 1) << 3);
#pragma unroll
            for (int kk = 0; kk < 4; kk++) {
                int ksg = (2 * kk + ((lane >> 3) & 1)) ^ (krow & 7);
                uint32_t ad = sstage + (uint32_t)(krow * 64 + ksg * 8) * 2;
                uint32_t bh0, bh1, bh2, bh3, bl0, bl1, bl2, bl3;
                ldm_x4(bh0, bh1, bh2, bh3, ad);
                ldm_x4(bl0, bl1, bl2, bl3, ad + 16384);
                uint32_t bb[2];
                bb[0] = bh0; bb[1] = bh1;
                mma16816(s[2*np],   qh[kk], bb);
                mma16816(s[2*np],   ql[kk], bb);
                bb[0] = bh2; bb[1] = bh3;
                mma16816(s[2*np+1], qh[kk], bb);
                mma16816(s[2*np+1], ql[kk], bb);
                bb[0] = bl0; bb[1] = bl1;
                mma16816(s[2*np],   qh[kk], bb);
                bb[0] = bl2; bb[1] = bl3;
                mma16816(s[2*np+1], qh[kk], bb);
            }
        }

        // mask (covers skipped tiles too: their s==0 entries become -1e30)
        const int rg0 = q0 + warp * 16 + (lane >> 2);
#pragma unroll
        for (int nt = 0; nt < 16; nt++) {
            int c0 = kbase + nt * 8 + 2 * (lane & 3);
            if (c0     > rg0)     s[nt][0] = -1e30f;
            if (c0 + 1 > rg0)     s[nt][1] = -1e30f;
            if (c0     > rg0 + 8) s[nt][2] = -1e30f;
            if (c0 + 1 > rg0 + 8) s[nt][3] = -1e30f;
        }

        float mx0 = -1e30f, mx1 = -1e30f;
#pragma unroll
        for (int nt = 0; nt < 16; nt++) {
            mx0 = fmaxf(mx0, fmaxf(s[nt][0], s[nt][1]));
            mx1 = fmaxf(mx1, fmaxf(s[nt][2], s[nt][3]));
        }
        mx0 = fmaxf(mx0, __shfl_xor_sync(0xffffffffu, mx0, 1));
        mx0 = fmaxf(mx0, __shfl_xor_sync(0xffffffffu, mx0, 2));
        mx1 = fmaxf(mx1, __shfl_xor_sync(0xffffffffu, mx1, 1));
        mx1 = fmaxf(mx1, __shfl_xor_sync(0xffffffffu, mx1, 2));
        float mn0 = fmaxf(m0, mx0), mn1 = fmaxf(m1, mx1);
        float cr0 = __expf(m0 - mn0), cr1 = __expf(m1 - mn1);
        m0 = mn0; m1 = mn1;
        float sum0 = 0.f, sum1 = 0.f;
#pragma unroll
        for (int nt = 0; nt < 16; nt++) {
            s[nt][0] = __expf(s[nt][0] - mn0);
            s[nt][1] = __expf(s[nt][1] - mn0);
            s[nt][2] = __expf(s[nt][2] - mn1);
            s[nt][3] = __expf(s[nt][3] - mn1);
            sum0 += s[nt][0] + s[nt][1];
            sum1 += s[nt][2] + s[nt][3];
        }
        sum0 += __shfl_xor_sync(0xffffffffu, sum0, 1);
        sum0 += __shfl_xor_sync(0xffffffffu, sum0, 2);
        sum1 += __shfl_xor_sync(0xffffffffu, sum1, 1);
        sum1 += __shfl_xor_sync(0xffffffffu, sum1, 2);
        l0 = l0 * cr0 + sum0;
        l1 = l1 * cr1 + sum1;
#pragma unroll
        for (int t = 0; t < 8; t++) {
            o[t][0] *= cr0; o[t][1] *= cr0; o[t][2] *= cr1; o[t][3] *= cr1;
        }

        // PV: only ks-tiles <= warp have P != 0
        for (int ks = 0; ks <= warp; ks++) {
            uint32_t ah[4], al[4];
            pack_hilo(s[2*ks][0],   s[2*ks][1],   ah[0], al[0]);
            pack_hilo(s[2*ks][2],   s[2*ks][3],   ah[1], al[1]);
            pack_hilo(s[2*ks+1][0], s[2*ks+1][1], ah[2], al[2]);
            pack_hilo(s[2*ks+1][2], s[2*ks+1][3], ah[3], al[3]);
            int vrow = ks * 16 + (lane & 15);
#pragma unroll
            for (int cp = 0; cp < 4; cp++) {
                int vsg = (2 * cp + (lane >> 4)) ^ (vrow & 7);
                uint32_t va = sstage + 32768 + (uint32_t)(vrow * 64 + vsg * 8) * 2;
                uint32_t vh0, vh1, vh2, vh3, vl0, vl1, vl2, vl3;
                ldm_x4_t(vh0, vh1, vh2, vh3, va);
                ldm_x4_t(vl0, vl1, vl2, vl3, va + 16384);
                uint32_t bb[2];
                bb[0] = vh0; bb[1] = vh1;
                mma16816(o[2*cp],   ah, bb);
                mma16816(o[2*cp],   al, bb);
                bb[0] = vl0; bb[1] = vl1;
                mma16816(o[2*cp],   ah, bb);
                bb[0] = vh2; bb[1] = vh3;
                mma16816(o[2*cp+1], ah, bb);
                mma16816(o[2*cp+1], al, bb);
                bb[0] = vl2; bb[1] = vl3;
                mma16816(o[2*cp+1], ah, bb);
            }
        }
    }

    // ---- epilogue: write [hi|lo] 2K layout
    const float inv0 = 1.f / l0, inv1 = 1.f / l1;
    const int rg0 = q0 + warp * 16 + (lane >> 2);
    const size_t ro0 = (size_t)(b * SEQ + rg0) * KE2;
    const size_t ro1 = (size_t)(b * SEQ + rg0 + 8) * KE2;
#pragma unroll
    for (int nt = 0; nt < 8; nt++) {
        int col = h * DK + nt * 8 + 2 * (lane & 3);
        uint32_t hi, lo;
        pack_hilo(o[nt][0] * inv0, o[nt][1] * inv0, hi, lo);
        *(uint32_t*)(atte + ro0 + col)          = hi;
        *(uint32_t*)(atte + ro0 + DMODEL + col) = lo;
        pack_hilo(o[nt][2] * inv1, o[nt][3] * inv1, hi, lo);
        *(uint32_t*)(atte + ro1 + col)          = hi;
        *(uint32_t*)(atte + ro1 + DMODEL + col) = lo;
    }
}

// ---------------------------------------------------------------------------
// kernel_launch
// ---------------------------------------------------------------------------
extern "C" void kernel_launch(void* const* d_in, const int* in_sizes, int n_in,
                              void* d_out, int out_size)
{
    const float* x     = (const float*)d_in[0];   // [2, 2048, 1024]
    const float* W_qkv = (const float*)d_in[1];   // [3072, 1024]
    const float* W_out = (const float*)d_in[2];   // [1024, 1024]
    float* out = (float*)d_out;                   // [2, 2048, 1024]

    __nv_bfloat16 *xe, *wqkve, *wute, *atte;
    cudaGetSymbolAddress((void**)&xe,    g_xe);
    cudaGetSymbolAddress((void**)&wqkve, g_wqkve);
    cudaGetSymbolAddress((void**)&wute,  g_wute);
    cudaGetSymbolAddress((void**)&atte,  g_atte);

    cudaFuncSetAttribute(gemm_bf16<0>, cudaFuncAttributeMaxDynamicSharedMemorySize, 3 * GSTAGE_BYTES);
    cudaFuncSetAttribute(gemm_bf16<1>, cudaFuncAttributeMaxDynamicSharedMemorySize, 3 * GSTAGE_BYTES);
    cudaFuncSetAttribute(attn_tc,      cudaFuncAttributeMaxDynamicSharedMemorySize, 131072);

    // 0) split conversions (inputs) -> [hi|lo] 2K layout
    {
        size_t tx_ = (size_t)MTOT * DMODEL;
        conv_split<<<(unsigned)((tx_/4 + 255)/256), 256>>>(x, xe, DMODEL, tx_);
        size_t tw = (size_t)QKV_N * DMODEL;
        conv_split<<<(unsigned)((tw/4 + 255)/256), 256>>>(W_qkv, wqkve, DMODEL, tw);
        size_t tu = (size_t)DMODEL * DMODEL;
        conv_split<<<(unsigned)((tu/4 + 255)/256), 256>>>(W_out, wute, DMODEL, tu);
    }
    // 1) QKV projection fused: writes Qhi/Qlo (scaled), Khi/Klo, Vhi/Vlo into g_kv
    {
        dim3 grid(QKV_N / 128, MTOT / 128);
        gemm_bf16<1><<<grid, 256, 3 * GSTAGE_BYTES>>>(xe, wqkve, nullptr, QKV_N);
    }
    // 2) tensor-core causal flash attention -> g_atte ([hi|lo] layout)
    {
        dim3 grid(SEQ / 128, NHEADS, BATCH);
        attn_tc<<<grid, 256, 131072>>>(atte);
    }
    // 3) output projection -> d_out
    {
        dim3 grid(DMODEL / 128, MTOT / 128);
        gemm_bf16<0><<<grid, 256, 3 * GSTAGE_BYTES>>>(atte, wute, out, DMODEL);
    }
}

// round 16
// speedup vs baseline: 1.1358x; 1.0183x over previous
#include <cuda_runtime.h>
#include <cuda_bf16.h>
#include <math.h>
#include <stdint.h>

// Problem constants
#define BATCH 2
#define SEQ   2048
#define DMODEL 1024
#define NHEADS 16
#define DK    64
#define MTOT  (BATCH*SEQ)          // 4096
#define QKV_N (3*DMODEL)           // 3072
#define KE2   (2*DMODEL)           // 2048: [hi | lo] layout width
#define KV_MS ((size_t)MTOT * DMODEL)   // per-matrix stride in g_kv

// Scratch (device globals — no allocation allowed)
__device__ __nv_bfloat16 g_xe   [(size_t)MTOT  * KE2];    // x      [hi|lo]
__device__ __nv_bfloat16 g_wqkve[(size_t)QKV_N * KE2];    // W_qkv  [hi|lo]
__device__ __nv_bfloat16 g_wute [(size_t)DMODEL* KE2];    // W_out  [hi|lo]
__device__ __nv_bfloat16 g_atte [(size_t)MTOT  * KE2];    // attn out [hi|lo]
// fused qkv output: [m][b*h][s][dk], m = {Qhi,Qlo,Khi,Klo,Vhi,Vlo} (Q pre-scaled)
__device__ __nv_bfloat16 g_kv[(size_t)6 * MTOT * DMODEL];

// ---------------------------------------------------------------------------
// helpers
// ---------------------------------------------------------------------------
__device__ __forceinline__ void pack_hilo(float a, float b, uint32_t& hi, uint32_t& lo)
{
    __nv_bfloat16 ha = __float2bfloat16_rn(a), hb = __float2bfloat16_rn(b);
    __nv_bfloat162 h; h.x = ha; h.y = hb;
    __nv_bfloat162 l;
    l.x = __float2bfloat16_rn(a - __bfloat162float(ha));
    l.y = __float2bfloat16_rn(b - __bfloat162float(hb));
    hi = *(uint32_t*)&h; lo = *(uint32_t*)&l;
}

__device__ __forceinline__ void ldm_x4(uint32_t& r0, uint32_t& r1, uint32_t& r2, uint32_t& r3,
                                       uint32_t addr)
{
    asm volatile("ldmatrix.sync.aligned.m8n8.x4.shared.b16 {%0,%1,%2,%3}, [%4];"
                 : "=r"(r0), "=r"(r1), "=r"(r2), "=r"(r3) : "r"(addr));
}

__device__ __forceinline__ void ldm_x4_t(uint32_t& r0, uint32_t& r1, uint32_t& r2, uint32_t& r3,
                                         uint32_t addr)
{
    asm volatile("ldmatrix.sync.aligned.m8n8.x4.trans.shared.b16 {%0,%1,%2,%3}, [%4];"
                 : "=r"(r0), "=r"(r1), "=r"(r2), "=r"(r3) : "r"(addr));
}

__device__ __forceinline__ void mma16816(float* d, const uint32_t* a, const uint32_t* b)
{
    asm volatile(
        "mma.sync.aligned.m16n8k16.row.col.f32.bf16.bf16.f32 "
        "{%0,%1,%2,%3}, {%4,%5,%6,%7}, {%8,%9}, {%0,%1,%2,%3};"
        : "+f"(d[0]), "+f"(d[1]), "+f"(d[2]), "+f"(d[3])
        : "r"(a[0]), "r"(a[1]), "r"(a[2]), "r"(a[3]), "r"(b[0]), "r"(b[1]));
}

__device__ __forceinline__ void cp16(uint32_t saddr, const void* gptr)
{
    asm volatile("cp.async.cg.shared.global [%0], [%1], 16;" :: "r"(saddr), "l"(gptr));
}

// ---------------------------------------------------------------------------
// Merged split-conversion for all three inputs (all K = DMODEL = 1024):
// rows [0,4096) -> g_xe, [4096,7168) -> g_wqkve, [7168,8192) -> g_wute.
// f32 [R,1024] -> bf16 [R,2048]  ([k]=hi, [1024+k]=lo)
// ---------------------------------------------------------------------------
__global__ void conv_split_all(const float* __restrict__ x,
                               const float* __restrict__ wqkv,
                               const float* __restrict__ wout)
{
    size_t idx = ((size_t)blockIdx.x * blockDim.x + threadIdx.x) * 4;  // over 8192*1024
    int r = (int)(idx >> 10);
    int k = (int)(idx & 1023);
    const float* src;
    __nv_bfloat16* dst;
    int row;
    if (r < MTOT)               { src = x;    dst = g_xe;    row = r; }
    else if (r < MTOT + QKV_N)  { src = wqkv; dst = g_wqkve; row = r - MTOT; }
    else                        { src = wout; dst = g_wute;  row = r - MTOT - QKV_N; }

    float4 v = *(const float4*)(src + (size_t)row * DMODEL + k);
    uint32_t hi01, hi23, lo01, lo23;
    pack_hilo(v.x, v.y, hi01, lo01);
    pack_hilo(v.z, v.w, hi23, lo23);
    __nv_bfloat16* o = dst + (size_t)row * KE2 + k;
    *(uint32_t*)(o + 0) = hi01;  *(uint32_t*)(o + 2) = hi23;
    *(uint32_t*)(o + DMODEL + 0) = lo01; *(uint32_t*)(o + DMODEL + 2) = lo23;
}

// ---------------------------------------------------------------------------
// bf16 tensor-core GEMM with 3-term fragment reuse, fragments loaded UPFRONT:
//   C = Ahi*Bhi^T + Alo*Bhi^T + Ahi*Blo^T   (fp32 accumulate)
// A,B stored [rows][2K]=[hi|lo]. 128x128 block, BK=32 real-K/step, 3-stage ring.
// FUSE=0: C f32 [M,N]. FUSE=1: smem-staged coalesced write to g_kv.
// ---------------------------------------------------------------------------
#define GSTAGE_BYTES 32768

template<int FUSE>
__global__ void __launch_bounds__(256, 2) gemm_bf16(
    const __nv_bfloat16* __restrict__ A, const __nv_bfloat16* __restrict__ B,
    float* __restrict__ C, int N)
{
    extern __shared__ __nv_bfloat16 gsm[];
    const uint32_t sbase = (uint32_t)__cvta_generic_to_shared(gsm);

    const int tid  = threadIdx.x;
    const int lane = tid & 31;
    const int warp = tid >> 5;
    const int wr = warp >> 2;
    const int wc = warp & 3;
    const int mBase = blockIdx.y * 128;
    const int nBase = blockIdx.x * 128;

    const int lrow = tid >> 2;
    const int lseg = tid & 3;
    const uint32_t swz0 = (uint32_t)(lrow * 32 + ((lseg ^ ((lrow >> 1) & 3)) * 8)) * 2;
    const uint32_t swz1 = (uint32_t)((lrow + 64) * 32 + ((lseg ^ (((lrow + 64) >> 1) & 3)) * 8)) * 2;
    const __nv_bfloat16* gA0 = A + (size_t)(mBase + lrow)      * KE2 + lseg * 8;
    const __nv_bfloat16* gA1 = A + (size_t)(mBase + lrow + 64) * KE2 + lseg * 8;
    const __nv_bfloat16* gB0 = B + (size_t)(nBase + lrow)      * KE2 + lseg * 8;
    const __nv_bfloat16* gB1 = B + (size_t)(nBase + lrow + 64) * KE2 + lseg * 8;

    const int arow = wr * 64 + (lane & 15);
    const int aseg = (lane >> 4) & 1;
    const int brow = wc * 32 + (lane & 7) + (((lane >> 4) & 1) << 3);
    const int bseg = (lane >> 3) & 1;

    float acc[4][4][4];
#pragma unroll
    for (int a = 0; a < 4; a++)
#pragma unroll
        for (int n = 0; n < 4; n++)
#pragma unroll
            for (int i = 0; i < 4; i++) acc[a][n][i] = 0.f;

    const int NSTEP = DMODEL / 32;     // 32 real-K steps

#pragma unroll
    for (int s = 0; s < 2; s++) {
        const uint32_t st = sbase + s * GSTAGE_BYTES;
        const int k0 = s * 32;
        cp16(st +          swz0, gA0 + k0);           cp16(st +          swz1, gA1 + k0);
        cp16(st +  8192 + swz0, gA0 + DMODEL + k0);   cp16(st +  8192 + swz1, gA1 + DMODEL + k0);
        cp16(st + 16384 + swz0, gB0 + k0);            cp16(st + 16384 + swz1, gB1 + k0);
        cp16(st + 24576 + swz0, gB0 + DMODEL + k0);   cp16(st + 24576 + swz1, gB1 + DMODEL + k0);
        asm volatile("cp.async.commit_group;");
    }

    int cur = 0, nxt = 2;
    for (int t = 0; t < NSTEP; t++) {
        if (t + 1 < NSTEP) asm volatile("cp.async.wait_group 1;");
        else               asm volatile("cp.async.wait_group 0;");
        __syncthreads();

        if (t + 2 < NSTEP) {
            const uint32_t st = sbase + nxt * GSTAGE_BYTES;
            const int k0 = (t + 2) * 32;
            cp16(st +          swz0, gA0 + k0);           cp16(st +          swz1, gA1 + k0);
            cp16(st +  8192 + swz0, gA0 + DMODEL + k0);   cp16(st +  8192 + swz1, gA1 + DMODEL + k0);
            cp16(st + 16384 + swz0, gB0 + k0);            cp16(st + 16384 + swz1, gB1 + k0);
            cp16(st + 24576 + swz0, gB0 + DMODEL + k0);   cp16(st + 24576 + swz1, gB1 + DMODEL + k0);
            asm volatile("cp.async.commit_group;");
        }

        const uint32_t stg = sbase + cur * GSTAGE_BYTES;

#pragma unroll
        for (int kk = 0; kk < 2; kk++) {
            // ---- load ALL fragments upfront (12 ldmatrix), then 48 mma
            uint32_t ah[4][4], al[4][4];
            uint32_t bh[4][2], bl[4][2];
#pragma unroll
            for (int a = 0; a < 4; a++) {
                int r = arow + a * 16;
                int seg = (kk * 2 + aseg) ^ ((r >> 1) & 3);
                uint32_t ad = stg + (uint32_t)(r * 32 + seg * 8) * 2;
                ldm_x4(ah[a][0], ah[a][1], ah[a][2], ah[a][3], ad);
                ldm_x4(al[a][0], al[a][1], al[a][2], al[a][3], ad + 8192);
            }
#pragma unroll
            for (int p = 0; p < 2; p++) {
                int n = brow + p * 16;
                int seg = (kk * 2 + bseg) ^ ((n >> 1) & 3);
                uint32_t ad = stg + 16384 + (uint32_t)(n * 32 + seg * 8) * 2;
                uint32_t r0, r1, r2, r3;
                ldm_x4(r0, r1, r2, r3, ad);
                bh[p * 2 + 0][0] = r0; bh[p * 2 + 0][1] = r1;
                bh[p * 2 + 1][0] = r2; bh[p * 2 + 1][1] = r3;
                ldm_x4(r0, r1, r2, r3, ad + 8192);
                bl[p * 2 + 0][0] = r0; bl[p * 2 + 0][1] = r1;
                bl[p * 2 + 1][0] = r2; bl[p * 2 + 1][1] = r3;
            }
#pragma unroll
            for (int a = 0; a < 4; a++)
#pragma unroll
                for (int n = 0; n < 4; n++)
                    mma16816(acc[a][n], ah[a], bh[n]);
#pragma unroll
            for (int a = 0; a < 4; a++)
#pragma unroll
                for (int n = 0; n < 4; n++)
                    mma16816(acc[a][n], al[a], bh[n]);
#pragma unroll
            for (int a = 0; a < 4; a++)
#pragma unroll
                for (int n = 0; n < 4; n++)
                    mma16816(acc[a][n], ah[a], bl[n]);
        }
        cur = (cur == 2) ? 0 : cur + 1;
        nxt = (nxt == 2) ? 0 : nxt + 1;
    }

    if (FUSE) {
        __syncthreads();
        const int region = nBase >> 10;                // 0=Q,1=K,2=V
        const int colbase = nBase & 1023;
        const float scale = (region == 0) ? 0.125f : 1.0f;
        char* smc = (char*)gsm;

#pragma unroll
        for (int a = 0; a < 4; a++) {
            int r0_ = wr * 64 + a * 16 + (lane >> 2);
#pragma unroll
            for (int n = 0; n < 4; n++) {
                int lcol = wc * 32 + n * 8 + (lane & 3) * 2;
                int chunk = lcol >> 3;
                int inb   = (lcol * 2) & 15;
                uint32_t hi, lo;
                pack_hilo(acc[a][n][0] * scale, acc[a][n][1] * scale, hi, lo);
                {
                    uint32_t byte = (uint32_t)r0_ * 256 + (((chunk ^ (r0_ & 7)) << 4) + inb);
                    *(uint32_t*)(smc + byte)         = hi;
                    *(uint32_t*)(smc + 32768 + byte) = lo;
                }
                pack_hilo(acc[a][n][2] * scale, acc[a][n][3] * scale, hi, lo);
                {
                    int r1_ = r0_ + 8;
                    uint32_t byte = (uint32_t)r1_ * 256 + (((chunk ^ (r1_ & 7)) << 4) + inb);
                    *(uint32_t*)(smc + byte)         = hi;
                    *(uint32_t*)(smc + 32768 + byte) = lo;
                }
            }
        }
        __syncthreads();

        __nv_bfloat16* mhi = g_kv + (size_t)(2 * region)     * KV_MS;
        __nv_bfloat16* mlo = g_kv + (size_t)(2 * region + 1) * KV_MS;
#pragma unroll
        for (int j = 0; j < 8; j++) {
            int it = tid + j * 256;
            int r_ = it >> 4;
            int ch = it & 15;
            uint32_t byte = (uint32_t)r_ * 256 + ((ch ^ (r_ & 7)) << 4);
            uint4 vh = *(uint4*)(smc + byte);
            uint4 vl = *(uint4*)(smc + 32768 + byte);
            int grow = mBase + r_;
            int col = colbase + ch * 8;
            int hh = col >> 6, dd = col & 63;
            int bb_ = grow >> 11, ss = grow & 2047;
            size_t dst = (((size_t)(bb_ * NHEADS + hh)) * SEQ + ss) * DK + dd;
            *(uint4*)&mhi[dst] = vh;
            *(uint4*)&mlo[dst] = vl;
        }
    } else {
#pragma unroll
        for (int a = 0; a < 4; a++) {
            int row0 = mBase + wr * 64 + a * 16 + (lane >> 2);
#pragma unroll
            for (int n = 0; n < 4; n++) {
                int col = nBase + wc * 32 + n * 8 + (lane & 3) * 2;
                *(float2*)&C[(size_t)row0 * N + col]       = make_float2(acc[a][n][0], acc[a][n][1]);
                *(float2*)&C[(size_t)(row0 + 8) * N + col] = make_float2(acc[a][n][2], acc[a][n][3]);
            }
        }
    }
}

// ---------------------------------------------------------------------------
// Tensor-core causal flash attention (frozen from R15): branch-free mainloop
// over non-diagonal tiles + peeled diagonal tile with triangular warp bounds.
// KB=128 K-tiles, 2 x 64KB cp.async stages, occupancy 1. Q from g_kv.
// ---------------------------------------------------------------------------
__device__ __forceinline__ void attn_prefetch(uint32_t dstbase, size_t bhoff,
                                              int krow0, int tid)
{
#pragma unroll
    for (int j = 0; j < 16; j++) {
        int c = tid + j * 256;            // 0..4095
        int m = c >> 10;                  // 0..3 -> mats 2..5 (Khi,Klo,Vhi,Vlo)
        int w = c & 1023;
        int r = w >> 3, sg = w & 7;
        uint32_t off = (uint32_t)(m * 16384) +
                       (uint32_t)(r * 64 + ((sg ^ (r & 7)) * 8)) * 2;
        cp16(dstbase + off,
             g_kv + (size_t)(m + 2) * KV_MS + bhoff + (size_t)(krow0 + r) * DK + sg * 8);
    }
}

__global__ void __launch_bounds__(256, 1) attn_tc(__nv_bfloat16* __restrict__ atte)
{
    extern __shared__ __nv_bfloat16 sm[];
    const uint32_t sbase = (uint32_t)__cvta_generic_to_shared(sm);

    const int b = blockIdx.z, h = blockIdx.y;
    const int qt = (int)(gridDim.x - 1 - blockIdx.x);   // heavy tiles first
    const int q0 = qt * 128;
    const int tid = threadIdx.x;
    const int lane = tid & 31, warp = tid >> 5;

    const size_t bhoff = ((size_t)(b * NHEADS + h)) * SEQ * DK;

#pragma unroll
    for (int j = 0; j < 8; j++) {
        int c = tid + j * 256;
        int m = c >> 10;                  // 0=Qhi,1=Qlo
        int w = c & 1023;
        int r = w >> 3, sg = w & 7;
        uint32_t off = (uint32_t)(m * 16384) +
                       (uint32_t)(r * 64 + ((sg ^ (r & 7)) * 8)) * 2;
        cp16(sbase + off,
             g_kv + (size_t)m * KV_MS + bhoff + (size_t)(q0 + r) * DK + sg * 8);
    }
    asm volatile("cp.async.commit_group;");
    attn_prefetch(sbase + 65536, bhoff, 0, tid);
    asm volatile("cp.async.commit_group;");
    asm volatile("cp.async.wait_group 1;");
    __syncthreads();

    uint32_t qh[4][4], ql[4][4];
    {
        const int r = warp * 16 + (lane & 15);
        const int sgx = lane >> 4;
#pragma unroll
        for (int ks = 0; ks < 4; ks++) {
            int sg = (2 * ks + sgx) ^ (r & 7);
            uint32_t ad = sbase + (uint32_t)(r * 64 + sg * 8) * 2;
            ldm_x4(qh[ks][0], qh[ks][1], qh[ks][2], qh[ks][3], ad);
            ldm_x4(ql[ks][0], ql[ks][1], ql[ks][2], ql[ks][3], ad + 16384);
        }
    }
    __syncthreads();

    float o[8][4];
#pragma unroll
    for (int t = 0; t < 8; t++) { o[t][0]=0.f; o[t][1]=0.f; o[t][2]=0.f; o[t][3]=0.f; }
    float m0 = -1e30f, m1 = -1e30f, l0 = 0.f, l1 = 0.f;

    for (int kt = 0; kt < qt; kt++) {
        const int kbase = kt * 128;
        attn_prefetch(sbase + (uint32_t)(kt & 1) * 65536, bhoff, kbase + 128, tid);
        asm volatile("cp.async.commit_group;");
        asm volatile("cp.async.wait_group 1;");
        __syncthreads();
        const uint32_t sstage = sbase + (uint32_t)((kt + 1) & 1) * 65536;

        float s[16][4];
#pragma unroll
        for (int t = 0; t < 16; t++) { s[t][0]=0.f; s[t][1]=0.f; s[t][2]=0.f; s[t][3]=0.f; }

#pragma unroll
        for (int kk = 0; kk < 4; kk++) {
#pragma unroll
            for (int np = 0; np < 8; np++) {
                int krow = np * 16 + (lane & 7) + (((lane >> 4) & 1) << 3);
                int ksg = (2 * kk + ((lane >> 3) & 1)) ^ (krow & 7);
                uint32_t ad = sstage + (uint32_t)(krow * 64 + ksg * 8) * 2;
                uint32_t bh0, bh1, bh2, bh3, bl0, bl1, bl2, bl3;
                ldm_x4(bh0, bh1, bh2, bh3, ad);
                ldm_x4(bl0, bl1, bl2, bl3, ad + 16384);
                uint32_t bb[2];
                bb[0] = bh0; bb[1] = bh1;
                mma16816(s[2*np],   qh[kk], bb);
                mma16816(s[2*np],   ql[kk], bb);
                bb[0] = bh2; bb[1] = bh3;
                mma16816(s[2*np+1], qh[kk], bb);
                mma16816(s[2*np+1], ql[kk], bb);
                bb[0] = bl0; bb[1] = bl1;
                mma16816(s[2*np],   qh[kk], bb);
                bb[0] = bl2; bb[1] = bl3;
                mma16816(s[2*np+1], qh[kk], bb);
            }
        }

        float mx0 = -1e30f, mx1 = -1e30f;
#pragma unroll
        for (int nt = 0; nt < 16; nt++) {
            mx0 = fmaxf(mx0, fmaxf(s[nt][0], s[nt][1]));
            mx1 = fmaxf(mx1, fmaxf(s[nt][2], s[nt][3]));
        }
        mx0 = fmaxf(mx0, __shfl_xor_sync(0xffffffffu, mx0, 1));
        mx0 = fmaxf(mx0, __shfl_xor_sync(0xffffffffu, mx0, 2));
        mx1 = fmaxf(mx1, __shfl_xor_sync(0xffffffffu, mx1, 1));
        mx1 = fmaxf(mx1, __shfl_xor_sync(0xffffffffu, mx1, 2));
        float mn0 = fmaxf(m0, mx0), mn1 = fmaxf(m1, mx1);
        float cr0 = __expf(m0 - mn0), cr1 = __expf(m1 - mn1);
        m0 = mn0; m1 = mn1;
        float sum0 = 0.f, sum1 = 0.f;
#pragma unroll
        for (int nt = 0; nt < 16; nt++) {
            s[nt][0] = __expf(s[nt][0] - mn0);
            s[nt][1] = __expf(s[nt][1] - mn0);
            s[nt][2] = __expf(s[nt][2] - mn1);
            s[nt][3] = __expf(s[nt][3] - mn1);
            sum0 += s[nt][0] + s[nt][1];
            sum1 += s[nt][2] + s[nt][3];
        }
        sum0 += __shfl_xor_sync(0xffffffffu, sum0, 1);
        sum0 += __shfl_xor_sync(0xffffffffu, sum0, 2);
        sum1 += __shfl_xor_sync(0xffffffffu, sum1, 1);
        sum1 += __shfl_xor_sync(0xffffffffu, sum1, 2);
        l0 = l0 * cr0 + sum0;
        l1 = l1 * cr1 + sum1;
#pragma unroll
        for (int t = 0; t < 8; t++) {
            o[t][0] *= cr0; o[t][1] *= cr0; o[t][2] *= cr1; o[t][3] *= cr1;
        }

#pragma unroll
        for (int ks = 0; ks < 8; ks++) {
            uint32_t ah[4], al[4];
            pack_hilo(s[2*ks][0],   s[2*ks][1],   ah[0], al[0]);
            pack_hilo(s[2*ks][2],   s[2*ks][3],   ah[1], al[1]);
            pack_hilo(s[2*ks+1][0], s[2*ks+1][1], ah[2], al[2]);
            pack_hilo(s[2*ks+1][2], s[2*ks+1][3], ah[3], al[3]);
#pragma unroll
            for (int cp = 0; cp < 4; cp++) {
                int vrow = ks * 16 + (lane & 15);
                int vsg = (2 * cp + (lane >> 4)) ^ (vrow & 7);
                uint32_t va = sstage + 32768 + (uint32_t)(vrow * 64 + vsg * 8) * 2;
                uint32_t vh0, vh1, vh2, vh3, vl0, vl1, vl2, vl3;
                ldm_x4_t(vh0, vh1, vh2, vh3, va);
                ldm_x4_t(vl0, vl1, vl2, vl3, va + 16384);
                uint32_t bb[2];
                bb[0] = vh0; bb[1] = vh1;
                mma16816(o[2*cp],   ah, bb);
                mma16816(o[2*cp],   al, bb);
                bb[0] = vl0; bb[1] = vl1;
                mma16816(o[2*cp],   ah, bb);
                bb[0] = vh2; bb[1] = vh3;
                mma16816(o[2*cp+1], ah, bb);
                mma16816(o[2*cp+1], al, bb);
                bb[0] = vl2; bb[1] = vl3;
                mma16816(o[2*cp+1], ah, bb);
            }
        }
        __syncthreads();
    }

    // ===== peeled diagonal tile (kt == qt)
    {
        const int kbase = qt * 128;
        asm volatile("cp.async.wait_group 0;");
        __syncthreads();
        const uint32_t sstage = sbase + (uint32_t)((qt + 1) & 1) * 65536;

        float s[16][4];
#pragma unroll
        for (int t = 0; t < 16; t++) { s[t][0]=0.f; s[t][1]=0.f; s[t][2]=0.f; s[t][3]=0.f; }

        for (int np = 0; np <= warp; np++) {
            int krow = np * 16 + (lane & 7) + (((lane >> 4) & 1) << 3);
#pragma unroll
            for (int kk = 0; kk < 4; kk++) {
                int ksg = (2 * kk + ((lane >> 3) & 1)) ^ (krow & 7);
                uint32_t ad = sstage + (uint32_t)(krow * 64 + ksg * 8) * 2;
                uint32_t bh0, bh1, bh2, bh3, bl0, bl1, bl2, bl3;
                ldm_x4(bh0, bh1, bh2, bh3, ad);
                ldm_x4(bl0, bl1, bl2, bl3, ad + 16384);
                uint32_t bb[2];
                bb[0] = bh0; bb[1] = bh1;
                mma16816(s[2*np],   qh[kk], bb);
                mma16816(s[2*np],   ql[kk], bb);
                bb[0] = bh2; bb[1] = bh3;
                mma16816(s[2*np+1], qh[kk], bb);
                mma16816(s[2*np+1], ql[kk], bb);
                bb[0] = bl0; bb[1] = bl1;
                mma16816(s[2*np],   qh[kk], bb);
                bb[0] = bl2; bb[1] = bl3;
                mma16816(s[2*np+1], qh[kk], bb);
            }
        }

        const int rg0 = q0 + warp * 16 + (lane >> 2);
#pragma unroll
        for (int nt = 0; nt < 16; nt++) {
            int c0 = kbase + nt * 8 + 2 * (lane & 3);
            if (c0     > rg0)     s[nt][0] = -1e30f;
            if (c0 + 1 > rg0)     s[nt][1] = -1e30f;
            if (c0     > rg0 + 8) s[nt][2] = -1e30f;
            if (c0 + 1 > rg0 + 8) s[nt][3] = -1e30f;
        }

        float mx0 = -1e30f, mx1 = -1e30f;
#pragma unroll
        for (int nt = 0; nt < 16; nt++) {
            mx0 = fmaxf(mx0, fmaxf(s[nt][0], s[nt][1]));
            mx1 = fmaxf(mx1, fmaxf(s[nt][2], s[nt][3]));
        }
        mx0 = fmaxf(mx0, __shfl_xor_sync(0xffffffffu, mx0, 1));
        mx0 = fmaxf(mx0, __shfl_xor_sync(0xffffffffu, mx0, 2));
        mx1 = fmaxf(mx1, __shfl_xor_sync(0xffffffffu, mx1, 1));
        mx1 = fmaxf(mx1, __shfl_xor_sync(0xffffffffu, mx1, 2));
        float mn0 = fmaxf(m0, mx0), mn1 = fmaxf(m1, mx1);
        float cr0 = __expf(m0 - mn0), cr1 = __expf(m1 - mn1);
        m0 = mn0; m1 = mn1;
        float sum0 = 0.f, sum1 = 0.f;
#pragma unroll
        for (int nt = 0; nt < 16; nt++) {
            s[nt][0] = __expf(s[nt][0] - mn0);
            s[nt][1] = __expf(s[nt][1] - mn0);
            s[nt][2] = __expf(s[nt][2] - mn1);
            s[nt][3] = __expf(s[nt][3] - mn1);
            sum0 += s[nt][0] + s[nt][1];
            sum1 += s[nt][2] + s[nt][3];
        }
        sum0 += __shfl_xor_sync(0xffffffffu, sum0, 1);
        sum0 += __shfl_xor_sync(0xffffffffu, sum0, 2);
        sum1 += __shfl_xor_sync(0xffffffffu, sum1, 1);
        sum1 += __shfl_xor_sync(0xffffffffu, sum1, 2);
        l0 = l0 * cr0 + sum0;
        l1 = l1 * cr1 + sum1;
#pragma unroll
        for (int t = 0; t < 8; t++) {
            o[t][0] *= cr0; o[t][1] *= cr0; o[t][2] *= cr1; o[t][3] *= cr1;
        }

        for (int ks = 0; ks <= warp; ks++) {
            uint32_t ah[4], al[4];
            pack_hilo(s[2*ks][0],   s[2*ks][1],   ah[0], al[0]);
            pack_hilo(s[2*ks][2],   s[2*ks][3],   ah[1], al[1]);
            pack_hilo(s[2*ks+1][0], s[2*ks+1][1], ah[2], al[2]);
            pack_hilo(s[2*ks+1][2], s[2*ks+1][3], ah[3], al[3]);
            int vrow = ks * 16 + (lane & 15);
#pragma unroll
            for (int cp = 0; cp < 4; cp++) {
                int vsg = (2 * cp + (lane >> 4)) ^ (vrow & 7);
                uint32_t va = sstage + 32768 + (uint32_t)(vrow * 64 + vsg * 8) * 2;
                uint32_t vh0, vh1, vh2, vh3, vl0, vl1, vl2, vl3;
                ldm_x4_t(vh0, vh1, vh2, vh3, va);
                ldm_x4_t(vl0, vl1, vl2, vl3, va + 16384);
                uint32_t bb[2];
                bb[0] = vh0; bb[1] = vh1;
                mma16816(o[2*cp],   ah, bb);
                mma16816(o[2*cp],   al, bb);
                bb[0] = vl0; bb[1] = vl1;
                mma16816(o[2*cp],   ah, bb);
                bb[0] = vh2; bb[1] = vh3;
                mma16816(o[2*cp+1], ah, bb);
                mma16816(o[2*cp+1], al, bb);
                bb[0] = vl2; bb[1] = vl3;
                mma16816(o[2*cp+1], ah, bb);
            }
        }
    }

    // ---- epilogue: write [hi|lo] 2K layout
    const float inv0 = 1.f / l0, inv1 = 1.f / l1;
    const int rg0 = q0 + warp * 16 + (lane >> 2);
    const size_t ro0 = (size_t)(b * SEQ + rg0) * KE2;
    const size_t ro1 = (size_t)(b * SEQ + rg0 + 8) * KE2;
#pragma unroll
    for (int nt = 0; nt < 8; nt++) {
        int col = h * DK + nt * 8 + 2 * (lane & 3);
        uint32_t hi, lo;
        pack_hilo(o[nt][0] * inv0, o[nt][1] * inv0, hi, lo);
        *(uint32_t*)(atte + ro0 + col)          = hi;
        *(uint32_t*)(atte + ro0 + DMODEL + col) = lo;
        pack_hilo(o[nt][2] * inv1, o[nt][3] * inv1, hi, lo);
        *(uint32_t*)(atte + ro1 + col)          = hi;
        *(uint32_t*)(atte + ro1 + DMODEL + col) = lo;
    }
}

// ---------------------------------------------------------------------------
// kernel_launch
// ---------------------------------------------------------------------------
extern "C" void kernel_launch(void* const* d_in, const int* in_sizes, int n_in,
                              void* d_out, int out_size)
{
    const float* x     = (const float*)d_in[0];   // [2, 2048, 1024]
    const float* W_qkv = (const float*)d_in[1];   // [3072, 1024]
    const float* W_out = (const float*)d_in[2];   // [1024, 1024]
    float* out = (float*)d_out;                   // [2, 2048, 1024]

    __nv_bfloat16 *xe, *wqkve, *wute, *atte;
    cudaGetSymbolAddress((void**)&xe,    g_xe);
    cudaGetSymbolAddress((void**)&wqkve, g_wqkve);
    cudaGetSymbolAddress((void**)&wute,  g_wute);
    cudaGetSymbolAddress((void**)&atte,  g_atte);

    cudaFuncSetAttribute(gemm_bf16<0>, cudaFuncAttributeMaxDynamicSharedMemorySize, 3 * GSTAGE_BYTES);
    cudaFuncSetAttribute(gemm_bf16<1>, cudaFuncAttributeMaxDynamicSharedMemorySize, 3 * GSTAGE_BYTES);
    cudaFuncSetAttribute(attn_tc,      cudaFuncAttributeMaxDynamicSharedMemorySize, 131072);

    // 0) merged split conversion: x, W_qkv, W_out -> [hi|lo] layouts
    {
        // 8192 rows x 1024 cols / 4 per thread = 2M threads
        conv_split_all<<<8192, 256>>>(x, W_qkv, W_out);
    }
    // 1) QKV projection fused: writes Qhi/Qlo (scaled), Khi/Klo, Vhi/Vlo into g_kv
    {
        dim3 grid(QKV_N / 128, MTOT / 128);
        gemm_bf16<1><<<grid, 256, 3 * GSTAGE_BYTES>>>(xe, wqkve, nullptr, QKV_N);
    }
    // 2) tensor-core causal flash attention -> g_atte ([hi|lo] layout)
    {
        dim3 grid(SEQ / 128, NHEADS, BATCH);
        attn_tc<<<grid, 256, 131072>>>(atte);
    }
    // 3) output projection -> d_out
    {
        dim3 grid(DMODEL / 128, MTOT / 128);
        gemm_bf16<0><<<grid, 256, 3 * GSTAGE_BYTES>>>(atte, wute, out, DMODEL);
    }
}

// round 17
// speedup vs baseline: 1.1545x; 1.0165x over previous
#include <cuda_runtime.h>
#include <cuda_bf16.h>
#include <math.h>
#include <stdint.h>

// Problem constants
#define BATCH 2
#define SEQ   2048
#define DMODEL 1024
#define NHEADS 16
#define DK    64
#define MTOT  (BATCH*SEQ)          // 4096
#define QKV_N (3*DMODEL)           // 3072
#define KE2   (2*DMODEL)           // 2048: [hi | lo] layout width
#define KV_MS ((size_t)MTOT * DMODEL)   // per-matrix stride in g_kv
// Q pre-scale folded with log2(e): softmax computed in exp2 domain.
#define QSCALE 0.18033688011112042f    // 0.125 * log2(e)

// Scratch (device globals — no allocation allowed)
__device__ __nv_bfloat16 g_xe   [(size_t)MTOT  * KE2];    // x      [hi|lo]
__device__ __nv_bfloat16 g_wqkve[(size_t)QKV_N * KE2];    // W_qkv  [hi|lo]
__device__ __nv_bfloat16 g_wute [(size_t)DMODEL* KE2];    // W_out  [hi|lo]
__device__ __nv_bfloat16 g_atte [(size_t)MTOT  * KE2];    // attn out [hi|lo]
// fused qkv output: [m][b*h][s][dk], m = {Qhi,Qlo,Khi,Klo,Vhi,Vlo} (Q pre-scaled)
__device__ __nv_bfloat16 g_kv[(size_t)6 * MTOT * DMODEL];

// ---------------------------------------------------------------------------
// helpers
// ---------------------------------------------------------------------------
__device__ __forceinline__ void pack_hilo(float a, float b, uint32_t& hi, uint32_t& lo)
{
    // hi = bf16x2{lo16=rn(a), hi16=rn(b)}; lo = bf16x2 of residuals.
    uint32_t h;
    asm("cvt.rn.bf16x2.f32 %0, %1, %2;" : "=r"(h) : "f"(b), "f"(a));
    float ra = __uint_as_float(h << 16);
    float rb = __uint_as_float(h & 0xffff0000u);
    float la = a - ra, lb = b - rb;
    uint32_t l;
    asm("cvt.rn.bf16x2.f32 %0, %1, %2;" : "=r"(l) : "f"(lb), "f"(la));
    hi = h; lo = l;
}

__device__ __forceinline__ float ex2f(float x)
{
    float y;
    asm("ex2.approx.ftz.f32 %0, %1;" : "=f"(y) : "f"(x));
    return y;
}

__device__ __forceinline__ void ldm_x4(uint32_t& r0, uint32_t& r1, uint32_t& r2, uint32_t& r3,
                                       uint32_t addr)
{
    asm volatile("ldmatrix.sync.aligned.m8n8.x4.shared.b16 {%0,%1,%2,%3}, [%4];"
                 : "=r"(r0), "=r"(r1), "=r"(r2), "=r"(r3) : "r"(addr));
}

__device__ __forceinline__ void ldm_x4_t(uint32_t& r0, uint32_t& r1, uint32_t& r2, uint32_t& r3,
                                         uint32_t addr)
{
    asm volatile("ldmatrix.sync.aligned.m8n8.x4.trans.shared.b16 {%0,%1,%2,%3}, [%4];"
                 : "=r"(r0), "=r"(r1), "=r"(r2), "=r"(r3) : "r"(addr));
}

__device__ __forceinline__ void mma16816(float* d, const uint32_t* a, const uint32_t* b)
{
    asm volatile(
        "mma.sync.aligned.m16n8k16.row.col.f32.bf16.bf16.f32 "
        "{%0,%1,%2,%3}, {%4,%5,%6,%7}, {%8,%9}, {%0,%1,%2,%3};"
        : "+f"(d[0]), "+f"(d[1]), "+f"(d[2]), "+f"(d[3])
        : "r"(a[0]), "r"(a[1]), "r"(a[2]), "r"(a[3]), "r"(b[0]), "r"(b[1]));
}

__device__ __forceinline__ void cp16(uint32_t saddr, const void* gptr)
{
    asm volatile("cp.async.cg.shared.global [%0], [%1], 16;" :: "r"(saddr), "l"(gptr));
}

// ---------------------------------------------------------------------------
// Merged split-conversion for all three inputs (all K = DMODEL = 1024):
// rows [0,4096) -> g_xe, [4096,7168) -> g_wqkve, [7168,8192) -> g_wute.
// ---------------------------------------------------------------------------
__global__ void conv_split_all(const float* __restrict__ x,
                               const float* __restrict__ wqkv,
                               const float* __restrict__ wout)
{
    size_t idx = ((size_t)blockIdx.x * blockDim.x + threadIdx.x) * 4;  // over 8192*1024
    int r = (int)(idx >> 10);
    int k = (int)(idx & 1023);
    const float* src;
    __nv_bfloat16* dst;
    int row;
    if (r < MTOT)               { src = x;    dst = g_xe;    row = r; }
    else if (r < MTOT + QKV_N)  { src = wqkv; dst = g_wqkve; row = r - MTOT; }
    else                        { src = wout; dst = g_wute;  row = r - MTOT - QKV_N; }

    float4 v = *(const float4*)(src + (size_t)row * DMODEL + k);
    uint32_t hi01, hi23, lo01, lo23;
    pack_hilo(v.x, v.y, hi01, lo01);
    pack_hilo(v.z, v.w, hi23, lo23);
    __nv_bfloat16* o = dst + (size_t)row * KE2 + k;
    *(uint32_t*)(o + 0) = hi01;  *(uint32_t*)(o + 2) = hi23;
    *(uint32_t*)(o + DMODEL + 0) = lo01; *(uint32_t*)(o + DMODEL + 2) = lo23;
}

// ---------------------------------------------------------------------------
// bf16 tensor-core GEMM with 3-term fragment reuse, fragments loaded upfront:
//   C = Ahi*Bhi^T + Alo*Bhi^T + Ahi*Blo^T   (fp32 accumulate)
// FUSE=0: C f32 [M,N]. FUSE=1: smem-staged coalesced write to g_kv.
// ---------------------------------------------------------------------------
#define GSTAGE_BYTES 32768

template<int FUSE>
__global__ void __launch_bounds__(256, 2) gemm_bf16(
    const __nv_bfloat16* __restrict__ A, const __nv_bfloat16* __restrict__ B,
    float* __restrict__ C, int N)
{
    extern __shared__ __nv_bfloat16 gsm[];
    const uint32_t sbase = (uint32_t)__cvta_generic_to_shared(gsm);

    const int tid  = threadIdx.x;
    const int lane = tid & 31;
    const int warp = tid >> 5;
    const int wr = warp >> 2;
    const int wc = warp & 3;
    const int mBase = blockIdx.y * 128;
    const int nBase = blockIdx.x * 128;

    const int lrow = tid >> 2;
    const int lseg = tid & 3;
    const uint32_t swz0 = (uint32_t)(lrow * 32 + ((lseg ^ ((lrow >> 1) & 3)) * 8)) * 2;
    const uint32_t swz1 = (uint32_t)((lrow + 64) * 32 + ((lseg ^ (((lrow + 64) >> 1) & 3)) * 8)) * 2;
    const __nv_bfloat16* gA0 = A + (size_t)(mBase + lrow)      * KE2 + lseg * 8;
    const __nv_bfloat16* gA1 = A + (size_t)(mBase + lrow + 64) * KE2 + lseg * 8;
    const __nv_bfloat16* gB0 = B + (size_t)(nBase + lrow)      * KE2 + lseg * 8;
    const __nv_bfloat16* gB1 = B + (size_t)(nBase + lrow + 64) * KE2 + lseg * 8;

    const int arow = wr * 64 + (lane & 15);
    const int aseg = (lane >> 4) & 1;
    const int brow = wc * 32 + (lane & 7) + (((lane >> 4) & 1) << 3);
    const int bseg = (lane >> 3) & 1;

    float acc[4][4][4];
#pragma unroll
    for (int a = 0; a < 4; a++)
#pragma unroll
        for (int n = 0; n < 4; n++)
#pragma unroll
            for (int i = 0; i < 4; i++) acc[a][n][i] = 0.f;

    const int NSTEP = DMODEL / 32;     // 32 real-K steps

#pragma unroll
    for (int s = 0; s < 2; s++) {
        const uint32_t st = sbase + s * GSTAGE_BYTES;
        const int k0 = s * 32;
        cp16(st +          swz0, gA0 + k0);           cp16(st +          swz1, gA1 + k0);
        cp16(st +  8192 + swz0, gA0 + DMODEL + k0);   cp16(st +  8192 + swz1, gA1 + DMODEL + k0);
        cp16(st + 16384 + swz0, gB0 + k0);            cp16(st + 16384 + swz1, gB1 + k0);
        cp16(st + 24576 + swz0, gB0 + DMODEL + k0);   cp16(st + 24576 + swz1, gB1 + DMODEL + k0);
        asm volatile("cp.async.commit_group;");
    }

    int cur = 0, nxt = 2;
    for (int t = 0; t < NSTEP; t++) {
        if (t + 1 < NSTEP) asm volatile("cp.async.wait_group 1;");
        else               asm volatile("cp.async.wait_group 0;");
        __syncthreads();

        if (t + 2 < NSTEP) {
            const uint32_t st = sbase + nxt * GSTAGE_BYTES;
            const int k0 = (t + 2) * 32;
            cp16(st +          swz0, gA0 + k0);           cp16(st +          swz1, gA1 + k0);
            cp16(st +  8192 + swz0, gA0 + DMODEL + k0);   cp16(st +  8192 + swz1, gA1 + DMODEL + k0);
            cp16(st + 16384 + swz0, gB0 + k0);            cp16(st + 16384 + swz1, gB1 + k0);
            cp16(st + 24576 + swz0, gB0 + DMODEL + k0);   cp16(st + 24576 + swz1, gB1 + DMODEL + k0);
            asm volatile("cp.async.commit_group;");
        }

        const uint32_t stg = sbase + cur * GSTAGE_BYTES;

#pragma unroll
        for (int kk = 0; kk < 2; kk++) {
            uint32_t ah[4][4], al[4][4];
            uint32_t bh[4][2], bl[4][2];
#pragma unroll
            for (int a = 0; a < 4; a++) {
                int r = arow + a * 16;
                int seg = (kk * 2 + aseg) ^ ((r >> 1) & 3);
                uint32_t ad = stg + (uint32_t)(r * 32 + seg * 8) * 2;
                ldm_x4(ah[a][0], ah[a][1], ah[a][2], ah[a][3], ad);
                ldm_x4(al[a][0], al[a][1], al[a][2], al[a][3], ad + 8192);
            }
#pragma unroll
            for (int p = 0; p < 2; p++) {
                int n = brow + p * 16;
                int seg = (kk * 2 + bseg) ^ ((n >> 1) & 3);
                uint32_t ad = stg + 16384 + (uint32_t)(n * 32 + seg * 8) * 2;
                uint32_t r0, r1, r2, r3;
                ldm_x4(r0, r1, r2, r3, ad);
                bh[p * 2 + 0][0] = r0; bh[p * 2 + 0][1] = r1;
                bh[p * 2 + 1][0] = r2; bh[p * 2 + 1][1] = r3;
                ldm_x4(r0, r1, r2, r3, ad + 8192);
                bl[p * 2 + 0][0] = r0; bl[p * 2 + 0][1] = r1;
                bl[p * 2 + 1][0] = r2; bl[p * 2 + 1][1] = r3;
            }
#pragma unroll
            for (int a = 0; a < 4; a++)
#pragma unroll
                for (int n = 0; n < 4; n++)
                    mma16816(acc[a][n], ah[a], bh[n]);
#pragma unroll
            for (int a = 0; a < 4; a++)
#pragma unroll
                for (int n = 0; n < 4; n++)
                    mma16816(acc[a][n], al[a], bh[n]);
#pragma unroll
            for (int a = 0; a < 4; a++)
#pragma unroll
                for (int n = 0; n < 4; n++)
                    mma16816(acc[a][n], ah[a], bl[n]);
        }
        cur = (cur == 2) ? 0 : cur + 1;
        nxt = (nxt == 2) ? 0 : nxt + 1;
    }

    if (FUSE) {
        __syncthreads();
        const int region = nBase >> 10;                // 0=Q,1=K,2=V
        const int colbase = nBase & 1023;
        const float scale = (region == 0) ? QSCALE : 1.0f;   // Q folded with log2(e)
        char* smc = (char*)gsm;

#pragma unroll
        for (int a = 0; a < 4; a++) {
            int r0_ = wr * 64 + a * 16 + (lane >> 2);
#pragma unroll
            for (int n = 0; n < 4; n++) {
                int lcol = wc * 32 + n * 8 + (lane & 3) * 2;
                int chunk = lcol >> 3;
                int inb   = (lcol * 2) & 15;
                uint32_t hi, lo;
                pack_hilo(acc[a][n][0] * scale, acc[a][n][1] * scale, hi, lo);
                {
                    uint32_t byte = (uint32_t)r0_ * 256 + (((chunk ^ (r0_ & 7)) << 4) + inb);
                    *(uint32_t*)(smc + byte)         = hi;
                    *(uint32_t*)(smc + 32768 + byte) = lo;
                }
                pack_hilo(acc[a][n][2] * scale, acc[a][n][3] * scale, hi, lo);
                {
                    int r1_ = r0_ + 8;
                    uint32_t byte = (uint32_t)r1_ * 256 + (((chunk ^ (r1_ & 7)) << 4) + inb);
                    *(uint32_t*)(smc + byte)         = hi;
                    *(uint32_t*)(smc + 32768 + byte) = lo;
                }
            }
        }
        __syncthreads();

        __nv_bfloat16* mhi = g_kv + (size_t)(2 * region)     * KV_MS;
        __nv_bfloat16* mlo = g_kv + (size_t)(2 * region + 1) * KV_MS;
#pragma unroll
        for (int j = 0; j < 8; j++) {
            int it = tid + j * 256;
            int r_ = it >> 4;
            int ch = it & 15;
            uint32_t byte = (uint32_t)r_ * 256 + ((ch ^ (r_ & 7)) << 4);
            uint4 vh = *(uint4*)(smc + byte);
            uint4 vl = *(uint4*)(smc + 32768 + byte);
            int grow = mBase + r_;
            int col = colbase + ch * 8;
            int hh = col >> 6, dd = col & 63;
            int bb_ = grow >> 11, ss = grow & 2047;
            size_t dst = (((size_t)(bb_ * NHEADS + hh)) * SEQ + ss) * DK + dd;
            *(uint4*)&mhi[dst] = vh;
            *(uint4*)&mlo[dst] = vl;
        }
    } else {
#pragma unroll
        for (int a = 0; a < 4; a++) {
            int row0 = mBase + wr * 64 + a * 16 + (lane >> 2);
#pragma unroll
            for (int n = 0; n < 4; n++) {
                int col = nBase + wc * 32 + n * 8 + (lane & 3) * 2;
                *(float2*)&C[(size_t)row0 * N + col]       = make_float2(acc[a][n][0], acc[a][n][1]);
                *(float2*)&C[(size_t)(row0 + 8) * N + col] = make_float2(acc[a][n][2], acc[a][n][3]);
            }
        }
    }
}

// ---------------------------------------------------------------------------
// Tensor-core causal flash attention (R15 structure; exp2-domain softmax).
// ---------------------------------------------------------------------------
__device__ __forceinline__ void attn_prefetch(uint32_t dstbase, size_t bhoff,
                                              int krow0, int tid)
{
#pragma unroll
    for (int j = 0; j < 16; j++) {
        int c = tid + j * 256;            // 0..4095
        int m = c >> 10;                  // 0..3 -> mats 2..5 (Khi,Klo,Vhi,Vlo)
        int w = c & 1023;
        int r = w >> 3, sg = w & 7;
        uint32_t off = (uint32_t)(m * 16384) +
                       (uint32_t)(r * 64 + ((sg ^ (r & 7)) * 8)) * 2;
        cp16(dstbase + off,
             g_kv + (size_t)(m + 2) * KV_MS + bhoff + (size_t)(krow0 + r) * DK + sg * 8);
    }
}

__global__ void __launch_bounds__(256, 1) attn_tc(__nv_bfloat16* __restrict__ atte)
{
    extern __shared__ __nv_bfloat16 sm[];
    const uint32_t sbase = (uint32_t)__cvta_generic_to_shared(sm);

    const int b = blockIdx.z, h = blockIdx.y;
    const int qt = (int)(gridDim.x - 1 - blockIdx.x);   // heavy tiles first
    const int q0 = qt * 128;
    const int tid = threadIdx.x;
    const int lane = tid & 31, warp = tid >> 5;

    const size_t bhoff = ((size_t)(b * NHEADS + h)) * SEQ * DK;

#pragma unroll
    for (int j = 0; j < 8; j++) {
        int c = tid + j * 256;
        int m = c >> 10;                  // 0=Qhi,1=Qlo
        int w = c & 1023;
        int r = w >> 3, sg = w & 7;
        uint32_t off = (uint32_t)(m * 16384) +
                       (uint32_t)(r * 64 + ((sg ^ (r & 7)) * 8)) * 2;
        cp16(sbase + off,
             g_kv + (size_t)m * KV_MS + bhoff + (size_t)(q0 + r) * DK + sg * 8);
    }
    asm volatile("cp.async.commit_group;");
    attn_prefetch(sbase + 65536, bhoff, 0, tid);
    asm volatile("cp.async.commit_group;");
    asm volatile("cp.async.wait_group 1;");
    __syncthreads();

    uint32_t qh[4][4], ql[4][4];
    {
        const int r = warp * 16 + (lane & 15);
        const int sgx = lane >> 4;
#pragma unroll
        for (int ks = 0; ks < 4; ks++) {
            int sg = (2 * ks + sgx) ^ (r & 7);
            uint32_t ad = sbase + (uint32_t)(r * 64 + sg * 8) * 2;
            ldm_x4(qh[ks][0], qh[ks][1], qh[ks][2], qh[ks][3], ad);
            ldm_x4(ql[ks][0], ql[ks][1], ql[ks][2], ql[ks][3], ad + 16384);
        }
    }
    __syncthreads();

    float o[8][4];
#pragma unroll
    for (int t = 0; t < 8; t++) { o[t][0]=0.f; o[t][1]=0.f; o[t][2]=0.f; o[t][3]=0.f; }
    float m0 = -1e30f, m1 = -1e30f, l0 = 0.f, l1 = 0.f;

    for (int kt = 0; kt < qt; kt++) {
        const int kbase = kt * 128;
        attn_prefetch(sbase + (uint32_t)(kt & 1) * 65536, bhoff, kbase + 128, tid);
        asm volatile("cp.async.commit_group;");
        asm volatile("cp.async.wait_group 1;");
        __syncthreads();
        const uint32_t sstage = sbase + (uint32_t)((kt + 1) & 1) * 65536;

        float s[16][4];
#pragma unroll
        for (int t = 0; t < 16; t++) { s[t][0]=0.f; s[t][1]=0.f; s[t][2]=0.f; s[t][3]=0.f; }

#pragma unroll
        for (int kk = 0; kk < 4; kk++) {
#pragma unroll
            for (int np = 0; np < 8; np++) {
                int krow = np * 16 + (lane & 7) + (((lane >> 4) & 1) << 3);
                int ksg = (2 * kk + ((lane >> 3) & 1)) ^ (krow & 7);
                uint32_t ad = sstage + (uint32_t)(krow * 64 + ksg * 8) * 2;
                uint32_t bh0, bh1, bh2, bh3, bl0, bl1, bl2, bl3;
                ldm_x4(bh0, bh1, bh2, bh3, ad);
                ldm_x4(bl0, bl1, bl2, bl3, ad + 16384);
                uint32_t bb[2];
                bb[0] = bh0; bb[1] = bh1;
                mma16816(s[2*np],   qh[kk], bb);
                mma16816(s[2*np],   ql[kk], bb);
                bb[0] = bh2; bb[1] = bh3;
                mma16816(s[2*np+1], qh[kk], bb);
                mma16816(s[2*np+1], ql[kk], bb);
                bb[0] = bl0; bb[1] = bl1;
                mma16816(s[2*np],   qh[kk], bb);
                bb[0] = bl2; bb[1] = bl3;
                mma16816(s[2*np+1], qh[kk], bb);
            }
        }

        float mx0 = -1e30f, mx1 = -1e30f;
#pragma unroll
        for (int nt = 0; nt < 16; nt++) {
            mx0 = fmaxf(mx0, fmaxf(s[nt][0], s[nt][1]));
            mx1 = fmaxf(mx1, fmaxf(s[nt][2], s[nt][3]));
        }
        mx0 = fmaxf(mx0, __shfl_xor_sync(0xffffffffu, mx0, 1));
        mx0 = fmaxf(mx0, __shfl_xor_sync(0xffffffffu, mx0, 2));
        mx1 = fmaxf(mx1, __shfl_xor_sync(0xffffffffu, mx1, 1));
        mx1 = fmaxf(mx1, __shfl_xor_sync(0xffffffffu, mx1, 2));
        float mn0 = fmaxf(m0, mx0), mn1 = fmaxf(m1, mx1);
        float cr0 = ex2f(m0 - mn0), cr1 = ex2f(m1 - mn1);
        m0 = mn0; m1 = mn1;
        float sum0 = 0.f, sum1 = 0.f;
#pragma unroll
        for (int nt = 0; nt < 16; nt++) {
            s[nt][0] = ex2f(s[nt][0] - mn0);
            s[nt][1] = ex2f(s[nt][1] - mn0);
            s[nt][2] = ex2f(s[nt][2] - mn1);
            s[nt][3] = ex2f(s[nt][3] - mn1);
            sum0 += s[nt][0] + s[nt][1];
            sum1 += s[nt][2] + s[nt][3];
        }
        sum0 += __shfl_xor_sync(0xffffffffu, sum0, 1);
        sum0 += __shfl_xor_sync(0xffffffffu, sum0, 2);
        sum1 += __shfl_xor_sync(0xffffffffu, sum1, 1);
        sum1 += __shfl_xor_sync(0xffffffffu, sum1, 2);
        l0 = l0 * cr0 + sum0;
        l1 = l1 * cr1 + sum1;
#pragma unroll
        for (int t = 0; t < 8; t++) {
            o[t][0] *= cr0; o[t][1] *= cr0; o[t][2] *= cr1; o[t][3] *= cr1;
        }

#pragma unroll
        for (int ks = 0; ks < 8; ks++) {
            uint32_t ah[4], al[4];
            pack_hilo(s[2*ks][0],   s[2*ks][1],   ah[0], al[0]);
            pack_hilo(s[2*ks][2],   s[2*ks][3],   ah[1], al[1]);
            pack_hilo(s[2*ks+1][0], s[2*ks+1][1], ah[2], al[2]);
            pack_hilo(s[2*ks+1][2], s[2*ks+1][3], ah[3], al[3]);
#pragma unroll
            for (int cp = 0; cp < 4; cp++) {
                int vrow = ks * 16 + (lane & 15);
                int vsg = (2 * cp + (lane >> 4)) ^ (vrow & 7);
                uint32_t va = sstage + 32768 + (uint32_t)(vrow * 64 + vsg * 8) * 2;
                uint32_t vh0, vh1, vh2, vh3, vl0, vl1, vl2, vl3;
                ldm_x4_t(vh0, vh1, vh2, vh3, va);
                ldm_x4_t(vl0, vl1, vl2, vl3, va + 16384);
                uint32_t bb[2];
                bb[0] = vh0; bb[1] = vh1;
                mma16816(o[2*cp],   ah, bb);
                mma16816(o[2*cp],   al, bb);
                bb[0] = vl0; bb[1] = vl1;
                mma16816(o[2*cp],   ah, bb);
                bb[0] = vh2; bb[1] = vh3;
                mma16816(o[2*cp+1], ah, bb);
                mma16816(o[2*cp+1], al, bb);
                bb[0] = vl2; bb[1] = vl3;
                mma16816(o[2*cp+1], ah, bb);
            }
        }
        __syncthreads();
    }

    // ===== peeled diagonal tile (kt == qt)
    {
        const int kbase = qt * 128;
        asm volatile("cp.async.wait_group 0;");
        __syncthreads();
        const uint32_t sstage = sbase + (uint32_t)((qt + 1) & 1) * 65536;

        float s[16][4];
#pragma unroll
        for (int t = 0; t < 16; t++) { s[t][0]=0.f; s[t][1]=0.f; s[t][2]=0.f; s[t][3]=0.f; }

        for (int np = 0; np <= warp; np++) {
            int krow = np * 16 + (lane & 7) + (((lane >> 4) & 1) << 3);
#pragma unroll
            for (int kk = 0; kk < 4; kk++) {
                int ksg = (2 * kk + ((lane >> 3) & 1)) ^ (krow & 7);
                uint32_t ad = sstage + (uint32_t)(krow * 64 + ksg * 8) * 2;
                uint32_t bh0, bh1, bh2, bh3, bl0, bl1, bl2, bl3;
                ldm_x4(bh0, bh1, bh2, bh3, ad);
                ldm_x4(bl0, bl1, bl2, bl3, ad + 16384);
                uint32_t bb[2];
                bb[0] = bh0; bb[1] = bh1;
                mma16816(s[2*np],   qh[kk], bb);
                mma16816(s[2*np],   ql[kk], bb);
                bb[0] = bh2; bb[1] = bh3;
                mma16816(s[2*np+1], qh[kk], bb);
                mma16816(s[2*np+1], ql[kk], bb);
                bb[0] = bl0; bb[1] = bl1;
                mma16816(s[2*np],   qh[kk], bb);
                bb[0] = bl2; bb[1] = bl3;
                mma16816(s[2*np+1], qh[kk], bb);
            }
        }

        const int rg0 = q0 + warp * 16 + (lane >> 2);
#pragma unroll
        for (int nt = 0; nt < 16; nt++) {
            int c0 = kbase + nt * 8 + 2 * (lane & 3);
            if (c0     > rg0)     s[nt][0] = -1e30f;
            if (c0 + 1 > rg0)     s[nt][1] = -1e30f;
            if (c0     > rg0 + 8) s[nt][2] = -1e30f;
            if (c0 + 1 > rg0 + 8) s[nt][3] = -1e30f;
        }

        float mx0 = -1e30f, mx1 = -1e30f;
#pragma unroll
        for (int nt = 0; nt < 16; nt++) {
            mx0 = fmaxf(mx0, fmaxf(s[nt][0], s[nt][1]));
            mx1 = fmaxf(mx1, fmaxf(s[nt][2], s[nt][3]));
        }
        mx0 = fmaxf(mx0, __shfl_xor_sync(0xffffffffu, mx0, 1));
        mx0 = fmaxf(mx0, __shfl_xor_sync(0xffffffffu, mx0, 2));
        mx1 = fmaxf(mx1, __shfl_xor_sync(0xffffffffu, mx1, 1));
        mx1 = fmaxf(mx1, __shfl_xor_sync(0xffffffffu, mx1, 2));
        float mn0 = fmaxf(m0, mx0), mn1 = fmaxf(m1, mx1);
        float cr0 = ex2f(m0 - mn0), cr1 = ex2f(m1 - mn1);
        m0 = mn0; m1 = mn1;
        float sum0 = 0.f, sum1 = 0.f;
#pragma unroll
        for (int nt = 0; nt < 16; nt++) {
            s[nt][0] = ex2f(s[nt][0] - mn0);
            s[nt][1] = ex2f(s[nt][1] - mn0);
            s[nt][2] = ex2f(s[nt][2] - mn1);
            s[nt][3] = ex2f(s[nt][3] - mn1);
            sum0 += s[nt][0] + s[nt][1];
            sum1 += s[nt][2] + s[nt][3];
        }
        sum0 += __shfl_xor_sync(0xffffffffu, sum0, 1);
        sum0 += __shfl_xor_sync(0xffffffffu, sum0, 2);
        sum1 += __shfl_xor_sync(0xffffffffu, sum1, 1);
        sum1 += __shfl_xor_sync(0xffffffffu, sum1, 2);
        l0 = l0 * cr0 + sum0;
        l1 = l1 * cr1 + sum1;
#pragma unroll
        for (int t = 0; t < 8; t++) {
            o[t][0] *= cr0; o[t][1] *= cr0; o[t][2] *= cr1; o[t][3] *= cr1;
        }

        for (int ks = 0; ks <= warp; ks++) {
            uint32_t ah[4], al[4];
            pack_hilo(s[2*ks][0],   s[2*ks][1],   ah[0], al[0]);
            pack_hilo(s[2*ks][2],   s[2*ks][3],   ah[1], al[1]);
            pack_hilo(s[2*ks+1][0], s[2*ks+1][1], ah[2], al[2]);
            pack_hilo(s[2*ks+1][2], s[2*ks+1][3], ah[3], al[3]);
            int vrow = ks * 16 + (lane & 15);
#pragma unroll
            for (int cp = 0; cp < 4; cp++) {
                int vsg = (2 * cp + (lane >> 4)) ^ (vrow & 7);
                uint32_t va = sstage + 32768 + (uint32_t)(vrow * 64 + vsg * 8) * 2;
                uint32_t vh0, vh1, vh2, vh3, vl0, vl1, vl2, vl3;
                ldm_x4_t(vh0, vh1, vh2, vh3, va);
                ldm_x4_t(vl0, vl1, vl2, vl3, va + 16384);
                uint32_t bb[2];
                bb[0] = vh0; bb[1] = vh1;
                mma16816(o[2*cp],   ah, bb);
                mma16816(o[2*cp],   al, bb);
                bb[0] = vl0; bb[1] = vl1;
                mma16816(o[2*cp],   ah, bb);
                bb[0] = vh2; bb[1] = vh3;
                mma16816(o[2*cp+1], ah, bb);
                mma16816(o[2*cp+1], al, bb);
                bb[0] = vl2; bb[1] = vl3;
                mma16816(o[2*cp+1], ah, bb);
            }
        }
    }

    // ---- epilogue: write [hi|lo] 2K layout
    const float inv0 = 1.f / l0, inv1 = 1.f / l1;
    const int rg0 = q0 + warp * 16 + (lane >> 2);
    const size_t ro0 = (size_t)(b * SEQ + rg0) * KE2;
    const size_t ro1 = (size_t)(b * SEQ + rg0 + 8) * KE2;
#pragma unroll
    for (int nt = 0; nt < 8; nt++) {
        int col = h * DK + nt * 8 + 2 * (lane & 3);
        uint32_t hi, lo;
        pack_hilo(o[nt][0] * inv0, o[nt][1] * inv0, hi, lo);
        *(uint32_t*)(atte + ro0 + col)          = hi;
        *(uint32_t*)(atte + ro0 + DMODEL + col) = lo;
        pack_hilo(o[nt][2] * inv1, o[nt][3] * inv1, hi, lo);
        *(uint32_t*)(atte + ro1 + col)          = hi;
        *(uint32_t*)(atte + ro1 + DMODEL + col) = lo;
    }
}

// ---------------------------------------------------------------------------
// kernel_launch
// ---------------------------------------------------------------------------
extern "C" void kernel_launch(void* const* d_in, const int* in_sizes, int n_in,
                              void* d_out, int out_size)
{
    const float* x     = (const float*)d_in[0];   // [2, 2048, 1024]
    const float* W_qkv = (const float*)d_in[1];   // [3072, 1024]
    const float* W_out = (const float*)d_in[2];   // [1024, 1024]
    float* out = (float*)d_out;                   // [2, 2048, 1024]

    __nv_bfloat16 *xe, *wqkve, *wute, *atte;
    cudaGetSymbolAddress((void**)&xe,    g_xe);
    cudaGetSymbolAddress((void**)&wqkve, g_wqkve);
    cudaGetSymbolAddress((void**)&wute,  g_wute);
    cudaGetSymbolAddress((void**)&atte,  g_atte);

    cudaFuncSetAttribute(gemm_bf16<0>, cudaFuncAttributeMaxDynamicSharedMemorySize, 3 * GSTAGE_BYTES);
    cudaFuncSetAttribute(gemm_bf16<1>, cudaFuncAttributeMaxDynamicSharedMemorySize, 3 * GSTAGE_BYTES);
    cudaFuncSetAttribute(attn_tc,      cudaFuncAttributeMaxDynamicSharedMemorySize, 131072);

    // 0) merged split conversion: x, W_qkv, W_out -> [hi|lo] layouts
    conv_split_all<<<8192, 256>>>(x, W_qkv, W_out);
    // 1) QKV projection fused: writes Qhi/Qlo (log2e-scaled), Khi/Klo, Vhi/Vlo
    {
        dim3 grid(QKV_N / 128, MTOT / 128);
        gemm_bf16<1><<<grid, 256, 3 * GSTAGE_BYTES>>>(xe, wqkve, nullptr, QKV_N);
    }
    // 2) tensor-core causal flash attention -> g_atte ([hi|lo] layout)
    {
        dim3 grid(SEQ / 128, NHEADS, BATCH);
        attn_tc<<<grid, 256, 131072>>>(atte);
    }
    // 3) output projection -> d_out
    {
        dim3 grid(DMODEL / 128, MTOT / 128);
        gemm_bf16<0><<<grid, 256, 3 * GSTAGE_BYTES>>>(atte, wute, out, DMODEL);
    }
}